// round 10
// baseline (speedup 1.0000x reference)
#include <cuda_runtime.h>
#include <cuda_fp16.h>
#include <stdint.h>

// ===========================================================================
// MoE-LoRA fused linear:  y = x @ W + (1/R) * (x @ A[l]) @ B[l] + bias
//   x: [T,D] f32, labels: [T] i32/i64, W: [D,D] f32, A: [E,D,R] f32,
//   B: [E,R,D] f32, bias: [D] f32, out: [T,D] f32.  T=16384 D=1024 R=8 E=64
//
// Round 10: fp16 single-pass GEMM with 64x64 warp tiles (256 threads,
// 2Mx4N warps, BM=128 BN=256). 128 accumulators/lane (fits 255-reg cap at
// 256 thr). Fragment reuse doubles: 128 B LDSM per MMA vs round 9's 256 B —
// attacks the measured L1=81% smem-crossbar bound.
// ===========================================================================

#define D_DIM 1024
#define R_DIM 8
#define SCALING 0.125f
#define MAX_T 16384

#define BM 128
#define BN 256
#define BKB 64                        // fp16 K per chunk
#define NSTAGE 4
#define NCHUNK 16                     // 1024 / 64
#define ROWSTRIDE 72                  // fp16 per smem row (64 + 8 pad) = 144 B
#define XPLANE_BYTES (128 * ROWSTRIDE * 2)    // 18432
#define WPLANE_BYTES (256 * ROWSTRIDE * 2)    // 36864
#define OFF_X 0
#define OFF_W (XPLANE_BYTES)
#define STAGE_BYTES (XPLANE_BYTES + WPLANE_BYTES)   // 55296
#define SMEM_BYTES (NSTAGE * STAGE_BYTES)           // 221184

// -------------------- device-global scratch (no allocs allowed) ------------
__device__ __align__(256) unsigned short g_x16[MAX_T * D_DIM];   // x fp16
__device__ __align__(256) unsigned short g_w16[D_DIM * D_DIM];   // W^T fp16
__device__ __align__(16)  float          g_xa[MAX_T * R_DIM];
__device__ int g_lab64;

// ------------------------------ helpers ------------------------------------
__device__ __forceinline__ uint32_t smem_u32(const void* p) {
    uint32_t a;
    asm("{ .reg .u64 t; cvta.to.shared.u64 t, %1; cvt.u32.u64 %0, t; }"
        : "=r"(a) : "l"(p));
    return a;
}
#define CP_ASYNC16(dst, src) \
    asm volatile("cp.async.cg.shared.global [%0], [%1], 16;" \
                 :: "r"(dst), "l"(src) : "memory")
#define CP_COMMIT() asm volatile("cp.async.commit_group;" ::: "memory")
#define CP_WAIT2()  asm volatile("cp.async.wait_group 2;" ::: "memory")
#define CP_WAIT0()  asm volatile("cp.async.wait_group 0;" ::: "memory")

#define LDSM4(r0, r1, r2, r3, addr) \
    asm volatile("ldmatrix.sync.aligned.m8n8.x4.shared.b16 {%0,%1,%2,%3}, [%4];" \
                 : "=r"(r0), "=r"(r1), "=r"(r2), "=r"(r3) : "r"(addr))

#define MMA16816F16(c, a, b) \
    asm volatile("mma.sync.aligned.m16n8k16.row.col.f32.f16.f16.f32 " \
                 "{%0,%1,%2,%3}, {%4,%5,%6,%7}, {%8,%9}, {%0,%1,%2,%3};" \
                 : "+f"((c)[0]), "+f"((c)[1]), "+f"((c)[2]), "+f"((c)[3]) \
                 : "r"((a)[0]), "r"((a)[1]), "r"((a)[2]), "r"((a)[3]), \
                   "r"((b)[0]), "r"((b)[1]))

// ---------------------------------------------------------------------------
// Kernel 0: classify labels dtype (int64 vs int32) deterministically.
// ---------------------------------------------------------------------------
__global__ void detect_label_dtype_kernel(const void* labels, int T) {
    if (threadIdx.x != 0 || blockIdx.x != 0) return;
    const long long* p = (const long long*)labels;
    int n = T < 256 ? T : 256;
    int is64 = 1;
    for (int i = 0; i < n; ++i) {
        long long v = p[i];
        if (v < 0 || v >= (1LL << 31)) { is64 = 0; break; }
    }
    g_lab64 = is64;
}
__device__ __forceinline__ int load_label(const void* labels, int t) {
    if (g_lab64) return (int)((const long long*)labels)[t];
    return ((const int*)labels)[t];
}

// ---------------------------------------------------------------------------
// Kernel 1: fused  x -> fp16  +  xa = x . A[label]   (one warp per token)
// ---------------------------------------------------------------------------
__global__ void __launch_bounds__(256)
convert_x_xa_kernel(const float* __restrict__ x,
                    const void*  __restrict__ labels,
                    const float* __restrict__ A, int T) {
    int t = blockIdx.x * 8 + (threadIdx.x >> 5);
    if (t >= T) return;
    const int lane = threadIdx.x & 31;
    const int e = load_label(labels, t);
    const float* xrow = x + (size_t)t * D_DIM;
    const float* Ae   = A + (size_t)e * D_DIM * R_DIM;
    unsigned short* xo = g_x16 + (size_t)t * D_DIM;

    float acc[R_DIM];
#pragma unroll
    for (int r = 0; r < R_DIM; ++r) acc[r] = 0.0f;

#pragma unroll
    for (int i = 0; i < 8; ++i) {
        const int d = i * 128 + lane * 4;
        float4 v = *(const float4*)(xrow + d);
        float vv[4] = {v.x, v.y, v.z, v.w};

        ushort4 h4;
        __half h;
        h = __float2half_rn(vv[0]); h4.x = *(unsigned short*)&h;
        h = __float2half_rn(vv[1]); h4.y = *(unsigned short*)&h;
        h = __float2half_rn(vv[2]); h4.z = *(unsigned short*)&h;
        h = __float2half_rn(vv[3]); h4.w = *(unsigned short*)&h;
        *(ushort4*)(xo + d) = h4;

#pragma unroll
        for (int j = 0; j < 4; ++j) {
            const float4* ap = (const float4*)(Ae + (size_t)(d + j) * R_DIM);
            float4 a0 = ap[0], a1 = ap[1];
            float xv = vv[j];
            acc[0] += xv * a0.x;  acc[1] += xv * a0.y;
            acc[2] += xv * a0.z;  acc[3] += xv * a0.w;
            acc[4] += xv * a1.x;  acc[5] += xv * a1.y;
            acc[6] += xv * a1.z;  acc[7] += xv * a1.w;
        }
    }
#pragma unroll
    for (int off = 16; off > 0; off >>= 1)
#pragma unroll
        for (int r = 0; r < R_DIM; ++r)
            acc[r] += __shfl_down_sync(0xffffffffu, acc[r], off);
    if (lane == 0) {
        float4* o = (float4*)(g_xa + (size_t)t * R_DIM);
        o[0] = make_float4(acc[0], acc[1], acc[2], acc[3]);
        o[1] = make_float4(acc[4], acc[5], acc[6], acc[7]);
    }
}

// ---------------------------------------------------------------------------
// Kernel 2: Wt[n][k] = fp16(W[k][n])
// ---------------------------------------------------------------------------
__global__ void __launch_bounds__(256)
convert_w_kernel(const float* __restrict__ W) {
    __shared__ float s[32][33];
    const int k0 = blockIdx.x * 32;
    const int n0 = blockIdx.y * 32;
    const int tx = threadIdx.x & 31;
    const int ty = threadIdx.x >> 5;
#pragma unroll
    for (int r = 0; r < 4; ++r) {
        int kk = ty + r * 8;
        s[kk][tx] = W[(size_t)(k0 + kk) * D_DIM + n0 + tx];
    }
    __syncthreads();
#pragma unroll
    for (int r = 0; r < 4; ++r) {
        int nn = ty + r * 8;
        __half h = __float2half_rn(s[tx][nn]);
        g_w16[(size_t)(n0 + nn) * D_DIM + k0 + tx] = *(unsigned short*)&h;
    }
}

// ---------------------------------------------------------------------------
// Kernel 3: fp16 GEMM + fused LoRA/bias epilogue.
//   256 threads = 8 warps (2M x 4N), warp tile 64x64, BM=128 BN=256.
//   128 accs/lane; 4-stage cp.async pipeline, prefetch before compute.
// ---------------------------------------------------------------------------
__global__ void __launch_bounds__(256, 1)
gemm_lora_kernel(const void*  __restrict__ labels,
                 const float* __restrict__ Bmat,
                 const float* __restrict__ bias,
                 float* __restrict__ out) {
    extern __shared__ char smem[];
    const uint32_t sbase = smem_u32(smem);
    const int tid  = threadIdx.x;
    const int row0 = blockIdx.y * BM;
    const int col0 = blockIdx.x * BN;

    // warp/lane geometry: 2M x 4N warps, each 64x64
    const int warp = tid >> 5, lane = tid & 31;
    const int wm = warp >> 2, wn = warp & 3;
    const uint32_t a_lm_base =
        (uint32_t)((wm * 64 + (lane & 15)) * ROWSTRIDE + (lane >> 4) * 8) * 2;
    const uint32_t b_lm_base =
        (uint32_t)((wn * 64 + (lane >> 4) * 8 + (lane & 7)) * ROWSTRIDE +
                   ((lane >> 3) & 1) * 8) * 2;

    float c[4][8][4];
#pragma unroll
    for (int i = 0; i < 4; ++i)
#pragma unroll
        for (int j = 0; j < 8; ++j)
#pragma unroll
            for (int q = 0; q < 4; ++q) c[i][j][q] = 0.0f;

    auto issue = [&](int cn) {
        const int kk = cn * BKB;
        const uint32_t sa = sbase + (uint32_t)(cn % NSTAGE) * STAGE_BYTES;
        // x plane: 128 rows x 8 segs = 1024 ops; 4 per thread
#pragma unroll
        for (int i = 0; i < 4; ++i) {
            const int idx = tid + i * 256;
            const int r = idx >> 3, s = idx & 7;
            CP_ASYNC16(sa + OFF_X + (uint32_t)(r * (ROWSTRIDE * 2) + s * 16),
                       g_x16 + (size_t)(row0 + r) * D_DIM + kk + s * 8);
        }
        // w plane: 256 rows x 8 segs = 2048 ops; 8 per thread
#pragma unroll
        for (int i = 0; i < 8; ++i) {
            const int idx = tid + i * 256;
            const int r = idx >> 3, s = idx & 7;
            CP_ASYNC16(sa + OFF_W + (uint32_t)(r * (ROWSTRIDE * 2) + s * 16),
                       g_w16 + (size_t)(col0 + r) * D_DIM + kk + s * 8);
        }
    };

    // prologue: fill 3 stages (prefetch distance 3)
#pragma unroll
    for (int cn = 0; cn < 3; ++cn) { issue(cn); CP_COMMIT(); }

    for (int ch = 0; ch < NCHUNK; ++ch) {
        CP_WAIT2();
        __syncthreads();

        if (ch + 3 < NCHUNK) { issue(ch + 3); }
        CP_COMMIT();

        const uint32_t sa = sbase + (uint32_t)(ch % NSTAGE) * STAGE_BYTES;

#pragma unroll
        for (int ks = 0; ks < 4; ++ks) {
            // B fragments: 8 nf (16 regs), 4 LDSM4
            uint32_t bfr[8][2];
#pragma unroll
            for (int p = 0; p < 4; ++p) {
                uint32_t bo = b_lm_base + (uint32_t)(p * 16 * ROWSTRIDE + ks * 16) * 2;
                uint32_t r0, r1, r2, r3;
                LDSM4(r0, r1, r2, r3, sa + OFF_W + bo);
                bfr[2 * p][0] = r0;      bfr[2 * p][1] = r1;
                bfr[2 * p + 1][0] = r2;  bfr[2 * p + 1][1] = r3;
            }
            // A fragments: 4 mf (16 regs), 4 LDSM4
            uint32_t afr[4][4];
#pragma unroll
            for (int mf = 0; mf < 4; ++mf) {
                uint32_t ao = a_lm_base + (uint32_t)(mf * 16 * ROWSTRIDE + ks * 16) * 2;
                LDSM4(afr[mf][0], afr[mf][1], afr[mf][2], afr[mf][3], sa + OFF_X + ao);
            }
            // 32 MMAs, all-distinct accumulators per sweep
#pragma unroll
            for (int mf = 0; mf < 4; ++mf)
#pragma unroll
                for (int nf = 0; nf < 8; ++nf)
                    MMA16816F16(c[mf][nf], afr[mf], bfr[nf]);
        }
    }
    CP_WAIT0();
    __syncthreads();

    // ---- stage accumulators to smem (reuse pipeline smem) ----
    float* acc_s = (float*)smem;                 // [128][260]
    const int g = lane >> 2, q = lane & 3;
#pragma unroll
    for (int mf = 0; mf < 4; ++mf) {
        const int r1 = wm * 64 + mf * 16 + g;
#pragma unroll
        for (int nf = 0; nf < 8; ++nf) {
            const int cc = wn * 64 + nf * 8 + q * 2;
            *(float2*)&acc_s[r1 * 260 + cc]       = make_float2(c[mf][nf][0], c[mf][nf][1]);
            *(float2*)&acc_s[(r1 + 8) * 260 + cc] = make_float2(c[mf][nf][2], c[mf][nf][3]);
        }
    }
    __syncthreads();

    // ---- epilogue: per-token rank-8 LoRA + bias ----
    // thread -> token lr = tid>>1 (0..127), column half = (tid&1)*128,
    // processed in four 32-col parts to bound registers.
    const int lr   = tid >> 1;
    const int half = (tid & 1) * 128;
    const int t    = row0 + lr;
    const int e    = load_label(labels, t);

    float xs[R_DIM];
    {
        const float4* p = (const float4*)(g_xa + (size_t)t * R_DIM);
        float4 a0 = p[0], a1 = p[1];
        xs[0] = SCALING * a0.x; xs[1] = SCALING * a0.y;
        xs[2] = SCALING * a0.z; xs[3] = SCALING * a0.w;
        xs[4] = SCALING * a1.x; xs[5] = SCALING * a1.y;
        xs[6] = SCALING * a1.z; xs[7] = SCALING * a1.w;
    }

    const float* Be0  = Bmat + (size_t)e * R_DIM * D_DIM + col0 + half;
    float*       orow = out  + (size_t)t * D_DIM + col0 + half;
    const float* brow = bias + col0 + half;

#pragma unroll
    for (int part = 0; part < 4; ++part) {
        const int pc = part * 32;
        float res[32];
#pragma unroll
        for (int v = 0; v < 8; ++v)
            *(float4*)&res[v * 4] = *(const float4*)&acc_s[lr * 260 + half + pc + v * 4];

#pragma unroll
        for (int r = 0; r < R_DIM; ++r) {
            const float4* bp = (const float4*)(Be0 + (size_t)r * D_DIM + pc);
            const float xr = xs[r];
#pragma unroll
            for (int v = 0; v < 8; ++v) {
                float4 b4 = bp[v];
                res[v * 4 + 0] += xr * b4.x;
                res[v * 4 + 1] += xr * b4.y;
                res[v * 4 + 2] += xr * b4.z;
                res[v * 4 + 3] += xr * b4.w;
            }
        }
        const float4* bi = (const float4*)(brow + pc);
#pragma unroll
        for (int v = 0; v < 8; ++v) {
            float4 bv = bi[v];
            float4 o4 = make_float4(res[v * 4 + 0] + bv.x, res[v * 4 + 1] + bv.y,
                                    res[v * 4 + 2] + bv.z, res[v * 4 + 3] + bv.w);
            ((float4*)(orow + pc))[v] = o4;
        }
    }
}

// ---------------------------------------------------------------------------
// kernel_launch — graph-capturable, allocation-free.
// Inputs: x, labels, W, A, B, bias
// ---------------------------------------------------------------------------
extern "C" void kernel_launch(void* const* d_in, const int* in_sizes, int n_in,
                              void* d_out, int out_size) {
    const float* x      = (const float*)d_in[0];
    const void*  labels = (const void*) d_in[1];
    const float* W      = (const float*)d_in[2];
    const float* A      = (const float*)d_in[3];
    const float* B      = (const float*)d_in[4];
    const float* bias   = (const float*)d_in[5];
    float* out          = (float*)d_out;

    const int T = in_sizes[0] / D_DIM;

    detect_label_dtype_kernel<<<1, 32>>>(labels, T);
    convert_x_xa_kernel<<<(T + 7) / 8, 256>>>(x, labels, A, T);
    convert_w_kernel<<<dim3(D_DIM / 32, D_DIM / 32), 256>>>(W);

    static int smem_set = 0;
    if (!smem_set) {
        cudaFuncSetAttribute(gemm_lora_kernel,
                             cudaFuncAttributeMaxDynamicSharedMemorySize, SMEM_BYTES);
        smem_set = 1;
    }
    dim3 grid(D_DIM / BN, T / BM);
    gemm_lora_kernel<<<grid, 256, SMEM_BYTES>>>(labels, B, bias, out);
}

// round 11
// speedup vs baseline: 1.0756x; 1.0756x over previous
#include <cuda_runtime.h>
#include <cuda_fp16.h>
#include <stdint.h>

// ===========================================================================
// MoE-LoRA fused linear:  y = x @ W + (1/R) * (x @ A[l]) @ B[l] + bias
//   x: [T,D] f32, labels: [T] i32/i64, W: [D,D] f32, A: [E,D,R] f32,
//   B: [E,R,D] f32, bias: [D] f32, out: [T,D] f32.  T=16384 D=1024 R=8 E=64
//
// Round 11: fp16 single-pass GEMM, 512 threads / 16 warps (4Mx4N of 64x32
// warp tiles), BM=256 BN=128. Combines R9's warp count (latency hiding) with
// improved fragment reuse: 192 B LDSM per MMA (R9: 256, R10: 128).
// 64 accs/lane + streamed A fragments stays under the 128-reg cap.
// ===========================================================================

#define D_DIM 1024
#define R_DIM 8
#define SCALING 0.125f
#define MAX_T 16384

#define BM 256
#define BN 128
#define BKB 64                        // fp16 K per chunk
#define NSTAGE 4
#define NCHUNK 16                     // 1024 / 64
#define ROWSTRIDE 72                  // fp16 per smem row (64 + 8 pad) = 144 B
#define APLANE_BYTES (256 * ROWSTRIDE * 2)    // 36864 (x: 256 rows)
#define BPLANE_BYTES (128 * ROWSTRIDE * 2)    // 18432 (w: 128 rows)
#define OFF_X 0
#define OFF_W (APLANE_BYTES)
#define STAGE_BYTES (APLANE_BYTES + BPLANE_BYTES)   // 55296
#define SMEM_BYTES (NSTAGE * STAGE_BYTES)           // 221184

// -------------------- device-global scratch (no allocs allowed) ------------
__device__ __align__(256) unsigned short g_x16[MAX_T * D_DIM];   // x fp16
__device__ __align__(256) unsigned short g_w16[D_DIM * D_DIM];   // W^T fp16
__device__ __align__(16)  float          g_xa[MAX_T * R_DIM];
__device__ int g_lab64;

// ------------------------------ helpers ------------------------------------
__device__ __forceinline__ uint32_t smem_u32(const void* p) {
    uint32_t a;
    asm("{ .reg .u64 t; cvta.to.shared.u64 t, %1; cvt.u32.u64 %0, t; }"
        : "=r"(a) : "l"(p));
    return a;
}
#define CP_ASYNC16(dst, src) \
    asm volatile("cp.async.cg.shared.global [%0], [%1], 16;" \
                 :: "r"(dst), "l"(src) : "memory")
#define CP_COMMIT() asm volatile("cp.async.commit_group;" ::: "memory")
#define CP_WAIT2()  asm volatile("cp.async.wait_group 2;" ::: "memory")
#define CP_WAIT0()  asm volatile("cp.async.wait_group 0;" ::: "memory")

#define LDSM4(r0, r1, r2, r3, addr) \
    asm volatile("ldmatrix.sync.aligned.m8n8.x4.shared.b16 {%0,%1,%2,%3}, [%4];" \
                 : "=r"(r0), "=r"(r1), "=r"(r2), "=r"(r3) : "r"(addr))

#define MMA16816F16(c, a, b) \
    asm volatile("mma.sync.aligned.m16n8k16.row.col.f32.f16.f16.f32 " \
                 "{%0,%1,%2,%3}, {%4,%5,%6,%7}, {%8,%9}, {%0,%1,%2,%3};" \
                 : "+f"((c)[0]), "+f"((c)[1]), "+f"((c)[2]), "+f"((c)[3]) \
                 : "r"((a)[0]), "r"((a)[1]), "r"((a)[2]), "r"((a)[3]), \
                   "r"((b)[0]), "r"((b)[1]))

// ---------------------------------------------------------------------------
// Kernel 0: classify labels dtype (int64 vs int32) deterministically.
// ---------------------------------------------------------------------------
__global__ void detect_label_dtype_kernel(const void* labels, int T) {
    if (threadIdx.x != 0 || blockIdx.x != 0) return;
    const long long* p = (const long long*)labels;
    int n = T < 256 ? T : 256;
    int is64 = 1;
    for (int i = 0; i < n; ++i) {
        long long v = p[i];
        if (v < 0 || v >= (1LL << 31)) { is64 = 0; break; }
    }
    g_lab64 = is64;
}
__device__ __forceinline__ int load_label(const void* labels, int t) {
    if (g_lab64) return (int)((const long long*)labels)[t];
    return ((const int*)labels)[t];
}

// ---------------------------------------------------------------------------
// Kernel 1: fused  x -> fp16  +  xa = x . A[label]   (one warp per token)
// ---------------------------------------------------------------------------
__global__ void __launch_bounds__(256)
convert_x_xa_kernel(const float* __restrict__ x,
                    const void*  __restrict__ labels,
                    const float* __restrict__ A, int T) {
    int t = blockIdx.x * 8 + (threadIdx.x >> 5);
    if (t >= T) return;
    const int lane = threadIdx.x & 31;
    const int e = load_label(labels, t);
    const float* xrow = x + (size_t)t * D_DIM;
    const float* Ae   = A + (size_t)e * D_DIM * R_DIM;
    unsigned short* xo = g_x16 + (size_t)t * D_DIM;

    float acc[R_DIM];
#pragma unroll
    for (int r = 0; r < R_DIM; ++r) acc[r] = 0.0f;

#pragma unroll
    for (int i = 0; i < 8; ++i) {
        const int d = i * 128 + lane * 4;
        float4 v = *(const float4*)(xrow + d);
        float vv[4] = {v.x, v.y, v.z, v.w};

        ushort4 h4;
        __half h;
        h = __float2half_rn(vv[0]); h4.x = *(unsigned short*)&h;
        h = __float2half_rn(vv[1]); h4.y = *(unsigned short*)&h;
        h = __float2half_rn(vv[2]); h4.z = *(unsigned short*)&h;
        h = __float2half_rn(vv[3]); h4.w = *(unsigned short*)&h;
        *(ushort4*)(xo + d) = h4;

#pragma unroll
        for (int j = 0; j < 4; ++j) {
            const float4* ap = (const float4*)(Ae + (size_t)(d + j) * R_DIM);
            float4 a0 = ap[0], a1 = ap[1];
            float xv = vv[j];
            acc[0] += xv * a0.x;  acc[1] += xv * a0.y;
            acc[2] += xv * a0.z;  acc[3] += xv * a0.w;
            acc[4] += xv * a1.x;  acc[5] += xv * a1.y;
            acc[6] += xv * a1.z;  acc[7] += xv * a1.w;
        }
    }
#pragma unroll
    for (int off = 16; off > 0; off >>= 1)
#pragma unroll
        for (int r = 0; r < R_DIM; ++r)
            acc[r] += __shfl_down_sync(0xffffffffu, acc[r], off);
    if (lane == 0) {
        float4* o = (float4*)(g_xa + (size_t)t * R_DIM);
        o[0] = make_float4(acc[0], acc[1], acc[2], acc[3]);
        o[1] = make_float4(acc[4], acc[5], acc[6], acc[7]);
    }
}

// ---------------------------------------------------------------------------
// Kernel 2: Wt[n][k] = fp16(W[k][n])
// ---------------------------------------------------------------------------
__global__ void __launch_bounds__(256)
convert_w_kernel(const float* __restrict__ W) {
    __shared__ float s[32][33];
    const int k0 = blockIdx.x * 32;
    const int n0 = blockIdx.y * 32;
    const int tx = threadIdx.x & 31;
    const int ty = threadIdx.x >> 5;
#pragma unroll
    for (int r = 0; r < 4; ++r) {
        int kk = ty + r * 8;
        s[kk][tx] = W[(size_t)(k0 + kk) * D_DIM + n0 + tx];
    }
    __syncthreads();
#pragma unroll
    for (int r = 0; r < 4; ++r) {
        int nn = ty + r * 8;
        __half h = __float2half_rn(s[tx][nn]);
        g_w16[(size_t)(n0 + nn) * D_DIM + k0 + tx] = *(unsigned short*)&h;
    }
}

// ---------------------------------------------------------------------------
// Kernel 3: fp16 GEMM + fused LoRA/bias epilogue.
//   512 threads = 16 warps (4M x 4N), warp tile 64x32, BM=256 BN=128.
//   64 accs/lane; B fragments resident, A streamed per m-frag.
// ---------------------------------------------------------------------------
__global__ void __launch_bounds__(512, 1)
gemm_lora_kernel(const void*  __restrict__ labels,
                 const float* __restrict__ Bmat,
                 const float* __restrict__ bias,
                 float* __restrict__ out) {
    extern __shared__ char smem[];
    const uint32_t sbase = smem_u32(smem);
    const int tid  = threadIdx.x;
    const int row0 = blockIdx.y * BM;
    const int col0 = blockIdx.x * BN;

    // warp/lane geometry: 4M x 4N warps, each 64x32
    const int warp = tid >> 5, lane = tid & 31;
    const int wm = warp >> 2, wn = warp & 3;
    const uint32_t a_lm_base =
        (uint32_t)((wm * 64 + (lane & 15)) * ROWSTRIDE + (lane >> 4) * 8) * 2;
    const uint32_t b_lm_base =
        (uint32_t)((wn * 32 + (lane >> 4) * 8 + (lane & 7)) * ROWSTRIDE +
                   ((lane >> 3) & 1) * 8) * 2;

    float c[4][4][4];                 // 64 accumulators
#pragma unroll
    for (int i = 0; i < 4; ++i)
#pragma unroll
        for (int j = 0; j < 4; ++j)
#pragma unroll
            for (int q = 0; q < 4; ++q) c[i][j][q] = 0.0f;

    auto issue = [&](int cn) {
        const int kk = cn * BKB;
        const uint32_t sa = sbase + (uint32_t)(cn % NSTAGE) * STAGE_BYTES;
        // x plane: 256 rows x 8 segs = 2048 ops; 4 per thread
#pragma unroll
        for (int i = 0; i < 4; ++i) {
            const int idx = tid + i * 512;
            const int r = idx >> 3, s = idx & 7;
            CP_ASYNC16(sa + OFF_X + (uint32_t)(r * (ROWSTRIDE * 2) + s * 16),
                       g_x16 + (size_t)(row0 + r) * D_DIM + kk + s * 8);
        }
        // w plane: 128 rows x 8 segs = 1024 ops; 2 per thread
#pragma unroll
        for (int i = 0; i < 2; ++i) {
            const int idx = tid + i * 512;
            const int r = idx >> 3, s = idx & 7;
            CP_ASYNC16(sa + OFF_W + (uint32_t)(r * (ROWSTRIDE * 2) + s * 16),
                       g_w16 + (size_t)(col0 + r) * D_DIM + kk + s * 8);
        }
    };

    // prologue: fill 3 stages (prefetch distance 3)
#pragma unroll
    for (int cn = 0; cn < 3; ++cn) { issue(cn); CP_COMMIT(); }

    for (int ch = 0; ch < NCHUNK; ++ch) {
        CP_WAIT2();
        __syncthreads();

        if (ch + 3 < NCHUNK) { issue(ch + 3); }
        CP_COMMIT();

        const uint32_t sa = sbase + (uint32_t)(ch % NSTAGE) * STAGE_BYTES;

#pragma unroll
        for (int ks = 0; ks < 4; ++ks) {
            // B fragments resident: 4 nf (8 regs), 2 LDSM4
            uint32_t bfr[4][2];
#pragma unroll
            for (int p = 0; p < 2; ++p) {
                uint32_t bo = b_lm_base + (uint32_t)(p * 16 * ROWSTRIDE + ks * 16) * 2;
                uint32_t r0, r1, r2, r3;
                LDSM4(r0, r1, r2, r3, sa + OFF_W + bo);
                bfr[2 * p][0] = r0;      bfr[2 * p][1] = r1;
                bfr[2 * p + 1][0] = r2;  bfr[2 * p + 1][1] = r3;
            }
            // stream A per m-frag: 1 LDSM4 (4 regs) then 4 MMAs, distinct accs
#pragma unroll
            for (int mf = 0; mf < 4; ++mf) {
                uint32_t ao = a_lm_base + (uint32_t)(mf * 16 * ROWSTRIDE + ks * 16) * 2;
                uint32_t afr[4];
                LDSM4(afr[0], afr[1], afr[2], afr[3], sa + OFF_X + ao);
#pragma unroll
                for (int nf = 0; nf < 4; ++nf)
                    MMA16816F16(c[mf][nf], afr, bfr[nf]);
            }
        }
    }
    CP_WAIT0();
    __syncthreads();

    // ---- stage accumulators to smem (reuse pipeline smem) ----
    float* acc_s = (float*)smem;                 // [256][132] = 135 KB
    const int g = lane >> 2, q = lane & 3;
#pragma unroll
    for (int mf = 0; mf < 4; ++mf) {
        const int r1 = wm * 64 + mf * 16 + g;
#pragma unroll
        for (int nf = 0; nf < 4; ++nf) {
            const int cc = wn * 32 + nf * 8 + q * 2;
            *(float2*)&acc_s[r1 * 132 + cc]       = make_float2(c[mf][nf][0], c[mf][nf][1]);
            *(float2*)&acc_s[(r1 + 8) * 132 + cc] = make_float2(c[mf][nf][2], c[mf][nf][3]);
        }
    }
    __syncthreads();

    // ---- epilogue: per-token rank-8 LoRA + bias ----
    // 512 threads, 256 tokens: 2 threads per token, 64 cols each.
    const int lr   = tid >> 1;           // 0..255
    const int half = (tid & 1) * 64;     // column half
    const int t    = row0 + lr;
    const int e    = load_label(labels, t);

    float xs[R_DIM];
    {
        const float4* p = (const float4*)(g_xa + (size_t)t * R_DIM);
        float4 a0 = p[0], a1 = p[1];
        xs[0] = SCALING * a0.x; xs[1] = SCALING * a0.y;
        xs[2] = SCALING * a0.z; xs[3] = SCALING * a0.w;
        xs[4] = SCALING * a1.x; xs[5] = SCALING * a1.y;
        xs[6] = SCALING * a1.z; xs[7] = SCALING * a1.w;
    }

    const float* Be   = Bmat + (size_t)e * R_DIM * D_DIM + col0 + half;
    float*       orow = out  + (size_t)t * D_DIM + col0 + half;
    const float* brow = bias + col0 + half;

#pragma unroll
    for (int part = 0; part < 2; ++part) {
        const int pc = part * 32;
        float res[32];
#pragma unroll
        for (int v = 0; v < 8; ++v)
            *(float4*)&res[v * 4] = *(const float4*)&acc_s[lr * 132 + half + pc + v * 4];

#pragma unroll
        for (int r = 0; r < R_DIM; ++r) {
            const float4* bp = (const float4*)(Be + (size_t)r * D_DIM + pc);
            const float xr = xs[r];
#pragma unroll
            for (int v = 0; v < 8; ++v) {
                float4 b4 = bp[v];
                res[v * 4 + 0] += xr * b4.x;
                res[v * 4 + 1] += xr * b4.y;
                res[v * 4 + 2] += xr * b4.z;
                res[v * 4 + 3] += xr * b4.w;
            }
        }
        const float4* bi = (const float4*)(brow + pc);
#pragma unroll
        for (int v = 0; v < 8; ++v) {
            float4 bv = bi[v];
            float4 o4 = make_float4(res[v * 4 + 0] + bv.x, res[v * 4 + 1] + bv.y,
                                    res[v * 4 + 2] + bv.z, res[v * 4 + 3] + bv.w);
            ((float4*)(orow + pc))[v] = o4;
        }
    }
}

// ---------------------------------------------------------------------------
// kernel_launch — graph-capturable, allocation-free.
// Inputs: x, labels, W, A, B, bias
// ---------------------------------------------------------------------------
extern "C" void kernel_launch(void* const* d_in, const int* in_sizes, int n_in,
                              void* d_out, int out_size) {
    const float* x      = (const float*)d_in[0];
    const void*  labels = (const void*) d_in[1];
    const float* W      = (const float*)d_in[2];
    const float* A      = (const float*)d_in[3];
    const float* B      = (const float*)d_in[4];
    const float* bias   = (const float*)d_in[5];
    float* out          = (float*)d_out;

    const int T = in_sizes[0] / D_DIM;

    detect_label_dtype_kernel<<<1, 32>>>(labels, T);
    convert_x_xa_kernel<<<(T + 7) / 8, 256>>>(x, labels, A, T);
    convert_w_kernel<<<dim3(D_DIM / 32, D_DIM / 32), 256>>>(W);

    static int smem_set = 0;
    if (!smem_set) {
        cudaFuncSetAttribute(gemm_lora_kernel,
                             cudaFuncAttributeMaxDynamicSharedMemorySize, SMEM_BYTES);
        smem_set = 1;
    }
    dim3 grid(D_DIM / BN, T / BM);
    gemm_lora_kernel<<<grid, 512, SMEM_BYTES>>>(labels, B, bias, out);
}

// round 12
// speedup vs baseline: 1.2525x; 1.1645x over previous
#include <cuda_runtime.h>
#include <cuda_fp16.h>
#include <stdint.h>

// ===========================================================================
// MoE-LoRA fused linear:  y = x @ W + (1/R) * (x @ A[l]) @ B[l] + bias
//   x: [T,D] f32, labels: [T] i32/i64, W: [D,D] f32, A: [E,D,R] f32,
//   B: [E,R,D] f32, bias: [D] f32, out: [T,D] f32.  T=16384 D=1024 R=8 E=64
//
// Round 12: EXACT round-9 geometry (fp16 single pass, 512 thr, 16 warps,
// 32x32 warp tiles, BM=BN=128, 5-stage cp.async) + REGISTER DOUBLE-BUFFERED
// fragments: LDSMs for ks+1 issue before the MMAs of ks, hiding the ~29-cyc
// shared-load latency that pinned issue at 8% in rounds 9-11.
// ===========================================================================

#define D_DIM 1024
#define R_DIM 8
#define SCALING 0.125f
#define MAX_T 16384

#define BM 128
#define BN 128
#define BKB 64                        // fp16 K per chunk
#define NSTAGE 5
#define NCHUNK 16                     // 1024 / 64
#define ROWSTRIDE 72                  // fp16 per smem row (64 + 8 pad) = 144 B
#define PLANE_BYTES (128 * ROWSTRIDE * 2)     // 18432
#define OFF_X 0
#define OFF_W (PLANE_BYTES)
#define STAGE_BYTES (2 * PLANE_BYTES)         // 36864
#define SMEM_BYTES (NSTAGE * STAGE_BYTES)     // 184320

// -------------------- device-global scratch (no allocs allowed) ------------
__device__ __align__(256) unsigned short g_x16[MAX_T * D_DIM];   // x fp16
__device__ __align__(256) unsigned short g_w16[D_DIM * D_DIM];   // W^T fp16
__device__ __align__(16)  float          g_xa[MAX_T * R_DIM];
__device__ int g_lab64;

// ------------------------------ helpers ------------------------------------
__device__ __forceinline__ uint32_t smem_u32(const void* p) {
    uint32_t a;
    asm("{ .reg .u64 t; cvta.to.shared.u64 t, %1; cvt.u32.u64 %0, t; }"
        : "=r"(a) : "l"(p));
    return a;
}
#define CP_ASYNC16(dst, src) \
    asm volatile("cp.async.cg.shared.global [%0], [%1], 16;" \
                 :: "r"(dst), "l"(src) : "memory")
#define CP_COMMIT() asm volatile("cp.async.commit_group;" ::: "memory")
#define CP_WAIT3()  asm volatile("cp.async.wait_group 3;" ::: "memory")
#define CP_WAIT0()  asm volatile("cp.async.wait_group 0;" ::: "memory")

#define LDSM4(r0, r1, r2, r3, addr) \
    asm volatile("ldmatrix.sync.aligned.m8n8.x4.shared.b16 {%0,%1,%2,%3}, [%4];" \
                 : "=r"(r0), "=r"(r1), "=r"(r2), "=r"(r3) : "r"(addr))

#define MMA16816F16(c, a, b) \
    asm volatile("mma.sync.aligned.m16n8k16.row.col.f32.f16.f16.f32 " \
                 "{%0,%1,%2,%3}, {%4,%5,%6,%7}, {%8,%9}, {%0,%1,%2,%3};" \
                 : "+f"((c)[0]), "+f"((c)[1]), "+f"((c)[2]), "+f"((c)[3]) \
                 : "r"((a)[0]), "r"((a)[1]), "r"((a)[2]), "r"((a)[3]), \
                   "r"((b)[0]), "r"((b)[1]))

// ---------------------------------------------------------------------------
// Kernel 0: classify labels dtype (int64 vs int32) deterministically.
// ---------------------------------------------------------------------------
__global__ void detect_label_dtype_kernel(const void* labels, int T) {
    if (threadIdx.x != 0 || blockIdx.x != 0) return;
    const long long* p = (const long long*)labels;
    int n = T < 256 ? T : 256;
    int is64 = 1;
    for (int i = 0; i < n; ++i) {
        long long v = p[i];
        if (v < 0 || v >= (1LL << 31)) { is64 = 0; break; }
    }
    g_lab64 = is64;
}
__device__ __forceinline__ int load_label(const void* labels, int t) {
    if (g_lab64) return (int)((const long long*)labels)[t];
    return ((const int*)labels)[t];
}

// ---------------------------------------------------------------------------
// Kernel 1: fused  x -> fp16  +  xa = x . A[label]   (one warp per token)
// ---------------------------------------------------------------------------
__global__ void __launch_bounds__(256)
convert_x_xa_kernel(const float* __restrict__ x,
                    const void*  __restrict__ labels,
                    const float* __restrict__ A, int T) {
    int t = blockIdx.x * 8 + (threadIdx.x >> 5);
    if (t >= T) return;
    const int lane = threadIdx.x & 31;
    const int e = load_label(labels, t);
    const float* xrow = x + (size_t)t * D_DIM;
    const float* Ae   = A + (size_t)e * D_DIM * R_DIM;
    unsigned short* xo = g_x16 + (size_t)t * D_DIM;

    float acc[R_DIM];
#pragma unroll
    for (int r = 0; r < R_DIM; ++r) acc[r] = 0.0f;

#pragma unroll
    for (int i = 0; i < 8; ++i) {
        const int d = i * 128 + lane * 4;
        float4 v = *(const float4*)(xrow + d);
        float vv[4] = {v.x, v.y, v.z, v.w};

        ushort4 h4;
        __half h;
        h = __float2half_rn(vv[0]); h4.x = *(unsigned short*)&h;
        h = __float2half_rn(vv[1]); h4.y = *(unsigned short*)&h;
        h = __float2half_rn(vv[2]); h4.z = *(unsigned short*)&h;
        h = __float2half_rn(vv[3]); h4.w = *(unsigned short*)&h;
        *(ushort4*)(xo + d) = h4;

#pragma unroll
        for (int j = 0; j < 4; ++j) {
            const float4* ap = (const float4*)(Ae + (size_t)(d + j) * R_DIM);
            float4 a0 = ap[0], a1 = ap[1];
            float xv = vv[j];
            acc[0] += xv * a0.x;  acc[1] += xv * a0.y;
            acc[2] += xv * a0.z;  acc[3] += xv * a0.w;
            acc[4] += xv * a1.x;  acc[5] += xv * a1.y;
            acc[6] += xv * a1.z;  acc[7] += xv * a1.w;
        }
    }
#pragma unroll
    for (int off = 16; off > 0; off >>= 1)
#pragma unroll
        for (int r = 0; r < R_DIM; ++r)
            acc[r] += __shfl_down_sync(0xffffffffu, acc[r], off);
    if (lane == 0) {
        float4* o = (float4*)(g_xa + (size_t)t * R_DIM);
        o[0] = make_float4(acc[0], acc[1], acc[2], acc[3]);
        o[1] = make_float4(acc[4], acc[5], acc[6], acc[7]);
    }
}

// ---------------------------------------------------------------------------
// Kernel 2: Wt[n][k] = fp16(W[k][n])
// ---------------------------------------------------------------------------
__global__ void __launch_bounds__(256)
convert_w_kernel(const float* __restrict__ W) {
    __shared__ float s[32][33];
    const int k0 = blockIdx.x * 32;
    const int n0 = blockIdx.y * 32;
    const int tx = threadIdx.x & 31;
    const int ty = threadIdx.x >> 5;
#pragma unroll
    for (int r = 0; r < 4; ++r) {
        int kk = ty + r * 8;
        s[kk][tx] = W[(size_t)(k0 + kk) * D_DIM + n0 + tx];
    }
    __syncthreads();
#pragma unroll
    for (int r = 0; r < 4; ++r) {
        int nn = ty + r * 8;
        __half h = __float2half_rn(s[tx][nn]);
        g_w16[(size_t)(n0 + nn) * D_DIM + k0 + tx] = *(unsigned short*)&h;
    }
}

// ---------------------------------------------------------------------------
// Kernel 3: fp16 GEMM + fused LoRA/bias epilogue.
//   512 threads = 16 warps (4M x 4N), warp tile 32x32, BM=BN=128.
//   5-stage cp.async; fragments double-buffered in registers across ks.
// ---------------------------------------------------------------------------
__global__ void __launch_bounds__(512, 1)
gemm_lora_kernel(const void*  __restrict__ labels,
                 const float* __restrict__ Bmat,
                 const float* __restrict__ bias,
                 float* __restrict__ out) {
    extern __shared__ char smem[];
    const uint32_t sbase = smem_u32(smem);
    const int tid  = threadIdx.x;
    const int row0 = blockIdx.y * BM;
    const int col0 = blockIdx.x * BN;

    // warp/lane geometry: 4M x 4N warps, each 32x32
    const int warp = tid >> 5, lane = tid & 31;
    const int wm = warp >> 2, wn = warp & 3;
    const uint32_t a_lm_base =
        (uint32_t)((wm * 32 + (lane & 15)) * ROWSTRIDE + (lane >> 4) * 8) * 2;
    const uint32_t b_lm_base =
        (uint32_t)((wn * 32 + (lane >> 4) * 8 + (lane & 7)) * ROWSTRIDE +
                   ((lane >> 3) & 1) * 8) * 2;

    float c[2][4][4];
#pragma unroll
    for (int i = 0; i < 2; ++i)
#pragma unroll
        for (int j = 0; j < 4; ++j)
#pragma unroll
            for (int q = 0; q < 4; ++q) c[i][j][q] = 0.0f;

    auto issue = [&](int cn) {
        const int kk = cn * BKB;
        const uint32_t sa = sbase + (uint32_t)(cn % NSTAGE) * STAGE_BYTES;
        const int lrow = tid >> 3;
        const int lseg = tid & 7;
#pragma unroll
        for (int h = 0; h < 2; ++h) {
            const int r = lrow + h * 64;
            const uint32_t doff = (uint32_t)(r * (ROWSTRIDE * 2) + lseg * 16);
            CP_ASYNC16(sa + OFF_X + doff,
                       g_x16 + (size_t)(row0 + r) * D_DIM + kk + lseg * 8);
            CP_ASYNC16(sa + OFF_W + doff,
                       g_w16 + (size_t)(col0 + r) * D_DIM + kk + lseg * 8);
        }
    };

    // prologue: fill 4 stages (prefetch distance 4)
#pragma unroll
    for (int cn = 0; cn < 4; ++cn) { issue(cn); CP_COMMIT(); }

    // fragment double buffers
    uint32_t bfr[2][4][2];   // [buf][nf][2]
    uint32_t afr[2][2][4];   // [buf][mf][4]

    for (int ch = 0; ch < NCHUNK; ++ch) {
        CP_WAIT3();
        __syncthreads();

        if (ch + 4 < NCHUNK) { issue(ch + 4); }
        CP_COMMIT();

        const uint32_t sa = sbase + (uint32_t)(ch % NSTAGE) * STAGE_BYTES;

        // load ks=0 fragments into buffer 0
#pragma unroll
        for (int p = 0; p < 2; ++p) {
            uint32_t bo = b_lm_base + (uint32_t)(p * 16 * ROWSTRIDE) * 2;
            uint32_t r0, r1, r2, r3;
            LDSM4(r0, r1, r2, r3, sa + OFF_W + bo);
            bfr[0][2 * p][0] = r0;      bfr[0][2 * p][1] = r1;
            bfr[0][2 * p + 1][0] = r2;  bfr[0][2 * p + 1][1] = r3;
        }
#pragma unroll
        for (int mf = 0; mf < 2; ++mf) {
            uint32_t ao = a_lm_base + (uint32_t)(mf * 16 * ROWSTRIDE) * 2;
            LDSM4(afr[0][mf][0], afr[0][mf][1], afr[0][mf][2], afr[0][mf][3],
                  sa + OFF_X + ao);
        }

#pragma unroll
        for (int ks = 0; ks < 4; ++ks) {
            const int cur = ks & 1;
            const int nxt = cur ^ 1;
            // prefetch ks+1 fragments into the other buffer (independent of
            // the MMAs below -> LDSM latency hidden behind 8 MMAs)
            if (ks < 3) {
#pragma unroll
                for (int p = 0; p < 2; ++p) {
                    uint32_t bo = b_lm_base +
                        (uint32_t)(p * 16 * ROWSTRIDE + (ks + 1) * 16) * 2;
                    uint32_t r0, r1, r2, r3;
                    LDSM4(r0, r1, r2, r3, sa + OFF_W + bo);
                    bfr[nxt][2 * p][0] = r0;      bfr[nxt][2 * p][1] = r1;
                    bfr[nxt][2 * p + 1][0] = r2;  bfr[nxt][2 * p + 1][1] = r3;
                }
#pragma unroll
                for (int mf = 0; mf < 2; ++mf) {
                    uint32_t ao = a_lm_base +
                        (uint32_t)(mf * 16 * ROWSTRIDE + (ks + 1) * 16) * 2;
                    LDSM4(afr[nxt][mf][0], afr[nxt][mf][1],
                          afr[nxt][mf][2], afr[nxt][mf][3], sa + OFF_X + ao);
                }
            }
            // 8 MMAs on the current buffer, all-distinct accumulators
#pragma unroll
            for (int mf = 0; mf < 2; ++mf)
#pragma unroll
                for (int nf = 0; nf < 4; ++nf)
                    MMA16816F16(c[mf][nf], afr[cur][mf], bfr[cur][nf]);
        }
    }
    CP_WAIT0();
    __syncthreads();

    // ---- stage accumulators to smem (reuse pipeline smem) ----
    float* acc_s = (float*)smem;                 // [128][132]
    const int g = lane >> 2, q = lane & 3;
#pragma unroll
    for (int mf = 0; mf < 2; ++mf) {
        const int r1 = wm * 32 + mf * 16 + g;
#pragma unroll
        for (int nf = 0; nf < 4; ++nf) {
            const int cc = wn * 32 + nf * 8 + q * 2;
            *(float2*)&acc_s[r1 * 132 + cc]       = make_float2(c[mf][nf][0], c[mf][nf][1]);
            *(float2*)&acc_s[(r1 + 8) * 132 + cc] = make_float2(c[mf][nf][2], c[mf][nf][3]);
        }
    }
    __syncthreads();

    // ---- epilogue: per-token rank-8 LoRA + bias, vectorized ----
    const int lr   = tid >> 2;           // 0..127
    const int qcol = (tid & 3) * 32;     // 32-col quarter
    const int t    = row0 + lr;
    const int e    = load_label(labels, t);

    float xs[R_DIM];
    {
        const float4* p = (const float4*)(g_xa + (size_t)t * R_DIM);
        float4 a0 = p[0], a1 = p[1];
        xs[0] = SCALING * a0.x; xs[1] = SCALING * a0.y;
        xs[2] = SCALING * a0.z; xs[3] = SCALING * a0.w;
        xs[4] = SCALING * a1.x; xs[5] = SCALING * a1.y;
        xs[6] = SCALING * a1.z; xs[7] = SCALING * a1.w;
    }

    float res[32];
#pragma unroll
    for (int v = 0; v < 8; ++v)
        *(float4*)&res[v * 4] = *(const float4*)&acc_s[lr * 132 + qcol + v * 4];

    const float* Be = Bmat + (size_t)e * R_DIM * D_DIM + col0 + qcol;
#pragma unroll
    for (int r = 0; r < R_DIM; ++r) {
        const float4* bp = (const float4*)(Be + (size_t)r * D_DIM);
        const float xr = xs[r];
#pragma unroll
        for (int v = 0; v < 8; ++v) {
            float4 b4 = bp[v];
            res[v * 4 + 0] += xr * b4.x;
            res[v * 4 + 1] += xr * b4.y;
            res[v * 4 + 2] += xr * b4.z;
            res[v * 4 + 3] += xr * b4.w;
        }
    }
    const float4* bi = (const float4*)(bias + col0 + qcol);
    float* op = out + (size_t)t * D_DIM + col0 + qcol;
#pragma unroll
    for (int v = 0; v < 8; ++v) {
        float4 bv = bi[v];
        float4 o4 = make_float4(res[v * 4 + 0] + bv.x, res[v * 4 + 1] + bv.y,
                                res[v * 4 + 2] + bv.z, res[v * 4 + 3] + bv.w);
        ((float4*)op)[v] = o4;
    }
}

// ---------------------------------------------------------------------------
// kernel_launch — graph-capturable, allocation-free.
// Inputs: x, labels, W, A, B, bias
// ---------------------------------------------------------------------------
extern "C" void kernel_launch(void* const* d_in, const int* in_sizes, int n_in,
                              void* d_out, int out_size) {
    const float* x      = (const float*)d_in[0];
    const void*  labels = (const void*) d_in[1];
    const float* W      = (const float*)d_in[2];
    const float* A      = (const float*)d_in[3];
    const float* B      = (const float*)d_in[4];
    const float* bias   = (const float*)d_in[5];
    float* out          = (float*)d_out;

    const int T = in_sizes[0] / D_DIM;

    detect_label_dtype_kernel<<<1, 32>>>(labels, T);
    convert_x_xa_kernel<<<(T + 7) / 8, 256>>>(x, labels, A, T);
    convert_w_kernel<<<dim3(D_DIM / 32, D_DIM / 32), 256>>>(W);

    static int smem_set = 0;
    if (!smem_set) {
        cudaFuncSetAttribute(gemm_lora_kernel,
                             cudaFuncAttributeMaxDynamicSharedMemorySize, SMEM_BYTES);
        smem_set = 1;
    }
    dim3 grid(D_DIM / BN, T / BM);
    gemm_lora_kernel<<<grid, 512, SMEM_BYTES>>>(labels, B, bias, out);
}

// round 13
// speedup vs baseline: 1.4051x; 1.1219x over previous
#include <cuda_runtime.h>
#include <cuda_fp16.h>
#include <stdint.h>

// ===========================================================================
// MoE-LoRA fused linear:  y = x @ W + (1/R) * (x @ A[l]) @ B[l] + bias
//   x: [T,D] f32, labels: [T] i32/i64, W: [D,D] f32, A: [E,D,R] f32,
//   B: [E,R,D] f32, bias: [D] f32, out: [T,D] f32.  T=16384 D=1024 R=8 E=64
//
// Round 13: fp16 GEMM, 512 thr / 16 warps, 64x32 warp tiles (BM=256 BN=128)
// with ALL fragments resident per ks (R9's independence, R11's reuse:
// 192 B LDSM per MMA). Epilogue LoRA-B gather in fp16 (halves ~512 MB of L2
// traffic that was ~19% of GEMM time).
// ===========================================================================

#define D_DIM 1024
#define R_DIM 8
#define SCALING 0.125f
#define MAX_T 16384
#define E_DIM 64

#define BM 256
#define BN 128
#define BKB 64                        // fp16 K per chunk
#define NSTAGE 4
#define NCHUNK 16                     // 1024 / 64
#define ROWSTRIDE 72                  // fp16 per smem row (64 + 8 pad) = 144 B
#define APLANE_BYTES (256 * ROWSTRIDE * 2)    // 36864 (x: 256 rows)
#define BPLANE_BYTES (128 * ROWSTRIDE * 2)    // 18432 (w: 128 rows)
#define OFF_X 0
#define OFF_W (APLANE_BYTES)
#define STAGE_BYTES (APLANE_BYTES + BPLANE_BYTES)   // 55296
#define SMEM_BYTES (NSTAGE * STAGE_BYTES)           // 221184

// -------------------- device-global scratch (no allocs allowed) ------------
__device__ __align__(256) unsigned short g_x16[MAX_T * D_DIM];   // x fp16
__device__ __align__(256) unsigned short g_w16[D_DIM * D_DIM];   // W^T fp16
__device__ __align__(256) unsigned short g_b16[E_DIM * R_DIM * D_DIM]; // B fp16
__device__ __align__(16)  float          g_xa[MAX_T * R_DIM];
__device__ int g_lab64;

// ------------------------------ helpers ------------------------------------
__device__ __forceinline__ uint32_t smem_u32(const void* p) {
    uint32_t a;
    asm("{ .reg .u64 t; cvta.to.shared.u64 t, %1; cvt.u32.u64 %0, t; }"
        : "=r"(a) : "l"(p));
    return a;
}
#define CP_ASYNC16(dst, src) \
    asm volatile("cp.async.cg.shared.global [%0], [%1], 16;" \
                 :: "r"(dst), "l"(src) : "memory")
#define CP_COMMIT() asm volatile("cp.async.commit_group;" ::: "memory")
#define CP_WAIT2()  asm volatile("cp.async.wait_group 2;" ::: "memory")
#define CP_WAIT0()  asm volatile("cp.async.wait_group 0;" ::: "memory")

#define LDSM4(r0, r1, r2, r3, addr) \
    asm volatile("ldmatrix.sync.aligned.m8n8.x4.shared.b16 {%0,%1,%2,%3}, [%4];" \
                 : "=r"(r0), "=r"(r1), "=r"(r2), "=r"(r3) : "r"(addr))

#define MMA16816F16(c, a, b) \
    asm volatile("mma.sync.aligned.m16n8k16.row.col.f32.f16.f16.f32 " \
                 "{%0,%1,%2,%3}, {%4,%5,%6,%7}, {%8,%9}, {%0,%1,%2,%3};" \
                 : "+f"((c)[0]), "+f"((c)[1]), "+f"((c)[2]), "+f"((c)[3]) \
                 : "r"((a)[0]), "r"((a)[1]), "r"((a)[2]), "r"((a)[3]), \
                   "r"((b)[0]), "r"((b)[1]))

// ---------------------------------------------------------------------------
// Kernel 0: classify labels dtype (int64 vs int32) deterministically.
// ---------------------------------------------------------------------------
__global__ void detect_label_dtype_kernel(const void* labels, int T) {
    if (threadIdx.x != 0 || blockIdx.x != 0) return;
    const long long* p = (const long long*)labels;
    int n = T < 256 ? T : 256;
    int is64 = 1;
    for (int i = 0; i < n; ++i) {
        long long v = p[i];
        if (v < 0 || v >= (1LL << 31)) { is64 = 0; break; }
    }
    g_lab64 = is64;
}
__device__ __forceinline__ int load_label(const void* labels, int t) {
    if (g_lab64) return (int)((const long long*)labels)[t];
    return ((const int*)labels)[t];
}

// ---------------------------------------------------------------------------
// Kernel 1: fused  x -> fp16  +  xa = x . A[label]   (one warp per token)
// ---------------------------------------------------------------------------
__global__ void __launch_bounds__(256)
convert_x_xa_kernel(const float* __restrict__ x,
                    const void*  __restrict__ labels,
                    const float* __restrict__ A, int T) {
    int t = blockIdx.x * 8 + (threadIdx.x >> 5);
    if (t >= T) return;
    const int lane = threadIdx.x & 31;
    const int e = load_label(labels, t);
    const float* xrow = x + (size_t)t * D_DIM;
    const float* Ae   = A + (size_t)e * D_DIM * R_DIM;
    unsigned short* xo = g_x16 + (size_t)t * D_DIM;

    float acc[R_DIM];
#pragma unroll
    for (int r = 0; r < R_DIM; ++r) acc[r] = 0.0f;

#pragma unroll
    for (int i = 0; i < 8; ++i) {
        const int d = i * 128 + lane * 4;
        float4 v = *(const float4*)(xrow + d);
        float vv[4] = {v.x, v.y, v.z, v.w};

        ushort4 h4;
        __half h;
        h = __float2half_rn(vv[0]); h4.x = *(unsigned short*)&h;
        h = __float2half_rn(vv[1]); h4.y = *(unsigned short*)&h;
        h = __float2half_rn(vv[2]); h4.z = *(unsigned short*)&h;
        h = __float2half_rn(vv[3]); h4.w = *(unsigned short*)&h;
        *(ushort4*)(xo + d) = h4;

#pragma unroll
        for (int j = 0; j < 4; ++j) {
            const float4* ap = (const float4*)(Ae + (size_t)(d + j) * R_DIM);
            float4 a0 = ap[0], a1 = ap[1];
            float xv = vv[j];
            acc[0] += xv * a0.x;  acc[1] += xv * a0.y;
            acc[2] += xv * a0.z;  acc[3] += xv * a0.w;
            acc[4] += xv * a1.x;  acc[5] += xv * a1.y;
            acc[6] += xv * a1.z;  acc[7] += xv * a1.w;
        }
    }
#pragma unroll
    for (int off = 16; off > 0; off >>= 1)
#pragma unroll
        for (int r = 0; r < R_DIM; ++r)
            acc[r] += __shfl_down_sync(0xffffffffu, acc[r], off);
    if (lane == 0) {
        float4* o = (float4*)(g_xa + (size_t)t * R_DIM);
        o[0] = make_float4(acc[0], acc[1], acc[2], acc[3]);
        o[1] = make_float4(acc[4], acc[5], acc[6], acc[7]);
    }
}

// ---------------------------------------------------------------------------
// Kernel 2: Wt[n][k] = fp16(W[k][n])
// ---------------------------------------------------------------------------
__global__ void __launch_bounds__(256)
convert_w_kernel(const float* __restrict__ W) {
    __shared__ float s[32][33];
    const int k0 = blockIdx.x * 32;
    const int n0 = blockIdx.y * 32;
    const int tx = threadIdx.x & 31;
    const int ty = threadIdx.x >> 5;
#pragma unroll
    for (int r = 0; r < 4; ++r) {
        int kk = ty + r * 8;
        s[kk][tx] = W[(size_t)(k0 + kk) * D_DIM + n0 + tx];
    }
    __syncthreads();
#pragma unroll
    for (int r = 0; r < 4; ++r) {
        int nn = ty + r * 8;
        __half h = __float2half_rn(s[tx][nn]);
        g_w16[(size_t)(n0 + nn) * D_DIM + k0 + tx] = *(unsigned short*)&h;
    }
}

// ---------------------------------------------------------------------------
// Kernel 2b: B -> fp16 (elementwise, 512K values)
// ---------------------------------------------------------------------------
__global__ void __launch_bounds__(256)
convert_b_kernel(const float* __restrict__ B, int n4) {
    int i = blockIdx.x * 256 + threadIdx.x;
    if (i >= n4) return;
    float4 v = ((const float4*)B)[i];
    __half2 h01 = __floats2half2_rn(v.x, v.y);
    __half2 h23 = __floats2half2_rn(v.z, v.w);
    uint2 o;
    o.x = *(uint32_t*)&h01;
    o.y = *(uint32_t*)&h23;
    ((uint2*)g_b16)[i] = o;
}

// ---------------------------------------------------------------------------
// Kernel 3: fp16 GEMM + fused LoRA/bias epilogue.
//   512 threads = 16 warps (4M x 4N), warp tile 64x32, BM=256 BN=128.
//   Per ks: 6 LDSM4 (all fragments resident) -> 16 independent MMAs.
// ---------------------------------------------------------------------------
__global__ void __launch_bounds__(512, 1)
gemm_lora_kernel(const void*  __restrict__ labels,
                 const float* __restrict__ bias,
                 float* __restrict__ out) {
    extern __shared__ char smem[];
    const uint32_t sbase = smem_u32(smem);
    const int tid  = threadIdx.x;
    const int row0 = blockIdx.y * BM;
    const int col0 = blockIdx.x * BN;

    // warp/lane geometry: 4M x 4N warps, each 64x32
    const int warp = tid >> 5, lane = tid & 31;
    const int wm = warp >> 2, wn = warp & 3;
    const uint32_t a_lm_base =
        (uint32_t)((wm * 64 + (lane & 15)) * ROWSTRIDE + (lane >> 4) * 8) * 2;
    const uint32_t b_lm_base =
        (uint32_t)((wn * 32 + (lane >> 4) * 8 + (lane & 7)) * ROWSTRIDE +
                   ((lane >> 3) & 1) * 8) * 2;

    float c[4][4][4];                 // 64 accumulators
#pragma unroll
    for (int i = 0; i < 4; ++i)
#pragma unroll
        for (int j = 0; j < 4; ++j)
#pragma unroll
            for (int q = 0; q < 4; ++q) c[i][j][q] = 0.0f;

    auto issue = [&](int cn) {
        const int kk = cn * BKB;
        const uint32_t sa = sbase + (uint32_t)(cn % NSTAGE) * STAGE_BYTES;
        // x plane: 256 rows x 8 segs = 2048 ops; 4 per thread
#pragma unroll
        for (int i = 0; i < 4; ++i) {
            const int idx = tid + i * 512;
            const int r = idx >> 3, s = idx & 7;
            CP_ASYNC16(sa + OFF_X + (uint32_t)(r * (ROWSTRIDE * 2) + s * 16),
                       g_x16 + (size_t)(row0 + r) * D_DIM + kk + s * 8);
        }
        // w plane: 128 rows x 8 segs = 1024 ops; 2 per thread
#pragma unroll
        for (int i = 0; i < 2; ++i) {
            const int idx = tid + i * 512;
            const int r = idx >> 3, s = idx & 7;
            CP_ASYNC16(sa + OFF_W + (uint32_t)(r * (ROWSTRIDE * 2) + s * 16),
                       g_w16 + (size_t)(col0 + r) * D_DIM + kk + s * 8);
        }
    };

    // prologue: fill 3 stages (prefetch distance 3)
#pragma unroll
    for (int cn = 0; cn < 3; ++cn) { issue(cn); CP_COMMIT(); }

    for (int ch = 0; ch < NCHUNK; ++ch) {
        CP_WAIT2();
        __syncthreads();

        if (ch + 3 < NCHUNK) { issue(ch + 3); }
        CP_COMMIT();

        const uint32_t sa = sbase + (uint32_t)(ch % NSTAGE) * STAGE_BYTES;

#pragma unroll
        for (int ks = 0; ks < 4; ++ks) {
            // ALL fragments resident: 2 B-LDSM4 + 4 A-LDSM4, then 16 MMAs
            uint32_t bfr[4][2];
#pragma unroll
            for (int p = 0; p < 2; ++p) {
                uint32_t bo = b_lm_base + (uint32_t)(p * 16 * ROWSTRIDE + ks * 16) * 2;
                uint32_t r0, r1, r2, r3;
                LDSM4(r0, r1, r2, r3, sa + OFF_W + bo);
                bfr[2 * p][0] = r0;      bfr[2 * p][1] = r1;
                bfr[2 * p + 1][0] = r2;  bfr[2 * p + 1][1] = r3;
            }
            uint32_t afr[4][4];
#pragma unroll
            for (int mf = 0; mf < 4; ++mf) {
                uint32_t ao = a_lm_base + (uint32_t)(mf * 16 * ROWSTRIDE + ks * 16) * 2;
                LDSM4(afr[mf][0], afr[mf][1], afr[mf][2], afr[mf][3], sa + OFF_X + ao);
            }
#pragma unroll
            for (int mf = 0; mf < 4; ++mf)
#pragma unroll
                for (int nf = 0; nf < 4; ++nf)
                    MMA16816F16(c[mf][nf], afr[mf], bfr[nf]);
        }
    }
    CP_WAIT0();
    __syncthreads();

    // ---- stage accumulators to smem (reuse pipeline smem) ----
    float* acc_s = (float*)smem;                 // [256][132] = 135 KB
    const int g = lane >> 2, q = lane & 3;
#pragma unroll
    for (int mf = 0; mf < 4; ++mf) {
        const int r1 = wm * 64 + mf * 16 + g;
#pragma unroll
        for (int nf = 0; nf < 4; ++nf) {
            const int cc = wn * 32 + nf * 8 + q * 2;
            *(float2*)&acc_s[r1 * 132 + cc]       = make_float2(c[mf][nf][0], c[mf][nf][1]);
            *(float2*)&acc_s[(r1 + 8) * 132 + cc] = make_float2(c[mf][nf][2], c[mf][nf][3]);
        }
    }
    __syncthreads();

    // ---- epilogue: per-token rank-8 LoRA (fp16 B) + bias ----
    // 512 threads, 256 tokens: 2 threads per token, 64 cols each.
    const int lr   = tid >> 1;           // 0..255
    const int half = (tid & 1) * 64;     // column half
    const int t    = row0 + lr;
    const int e    = load_label(labels, t);

    float xs[R_DIM];
    {
        const float4* p = (const float4*)(g_xa + (size_t)t * R_DIM);
        float4 a0 = p[0], a1 = p[1];
        xs[0] = SCALING * a0.x; xs[1] = SCALING * a0.y;
        xs[2] = SCALING * a0.z; xs[3] = SCALING * a0.w;
        xs[4] = SCALING * a1.x; xs[5] = SCALING * a1.y;
        xs[6] = SCALING * a1.z; xs[7] = SCALING * a1.w;
    }

    const unsigned short* Be = g_b16 + (size_t)e * R_DIM * D_DIM + col0 + half;
    float*       orow = out  + (size_t)t * D_DIM + col0 + half;
    const float* brow = bias + col0 + half;

#pragma unroll
    for (int part = 0; part < 2; ++part) {
        const int pc = part * 32;
        float res[32];
#pragma unroll
        for (int v = 0; v < 8; ++v)
            *(float4*)&res[v * 4] = *(const float4*)&acc_s[lr * 132 + half + pc + v * 4];

#pragma unroll
        for (int r = 0; r < R_DIM; ++r) {
            const uint4* bp = (const uint4*)(Be + (size_t)r * D_DIM + pc); // 32 fp16 = 4 uint4
            const float xr = xs[r];
#pragma unroll
            for (int v = 0; v < 4; ++v) {
                uint4 q4 = bp[v];
                float2 f0 = __half22float2(*(__half2*)&q4.x);
                float2 f1 = __half22float2(*(__half2*)&q4.y);
                float2 f2 = __half22float2(*(__half2*)&q4.z);
                float2 f3 = __half22float2(*(__half2*)&q4.w);
                res[v * 8 + 0] += xr * f0.x;  res[v * 8 + 1] += xr * f0.y;
                res[v * 8 + 2] += xr * f1.x;  res[v * 8 + 3] += xr * f1.y;
                res[v * 8 + 4] += xr * f2.x;  res[v * 8 + 5] += xr * f2.y;
                res[v * 8 + 6] += xr * f3.x;  res[v * 8 + 7] += xr * f3.y;
            }
        }
        const float4* bi = (const float4*)(brow + pc);
#pragma unroll
        for (int v = 0; v < 8; ++v) {
            float4 bv = bi[v];
            float4 o4 = make_float4(res[v * 4 + 0] + bv.x, res[v * 4 + 1] + bv.y,
                                    res[v * 4 + 2] + bv.z, res[v * 4 + 3] + bv.w);
            ((float4*)(orow + pc))[v] = o4;
        }
    }
}

// ---------------------------------------------------------------------------
// kernel_launch — graph-capturable, allocation-free.
// Inputs: x, labels, W, A, B, bias
// ---------------------------------------------------------------------------
extern "C" void kernel_launch(void* const* d_in, const int* in_sizes, int n_in,
                              void* d_out, int out_size) {
    const float* x      = (const float*)d_in[0];
    const void*  labels = (const void*) d_in[1];
    const float* W      = (const float*)d_in[2];
    const float* A      = (const float*)d_in[3];
    const float* B      = (const float*)d_in[4];
    const float* bias   = (const float*)d_in[5];
    float* out          = (float*)d_out;

    const int T = in_sizes[0] / D_DIM;

    detect_label_dtype_kernel<<<1, 32>>>(labels, T);
    convert_x_xa_kernel<<<(T + 7) / 8, 256>>>(x, labels, A, T);
    convert_w_kernel<<<dim3(D_DIM / 32, D_DIM / 32), 256>>>(W);
    convert_b_kernel<<<(E_DIM * R_DIM * D_DIM / 4 + 255) / 256, 256>>>(
        B, E_DIM * R_DIM * D_DIM / 4);

    static int smem_set = 0;
    if (!smem_set) {
        cudaFuncSetAttribute(gemm_lora_kernel,
                             cudaFuncAttributeMaxDynamicSharedMemorySize, SMEM_BYTES);
        smem_set = 1;
    }
    dim3 grid(D_DIM / BN, T / BM);
    gemm_lora_kernel<<<grid, 512, SMEM_BYTES>>>(labels, bias, out);
}

// round 14
// speedup vs baseline: 1.9858x; 1.4133x over previous
#include <cuda_runtime.h>
#include <cuda_fp16.h>
#include <stdint.h>

// ===========================================================================
// MoE-LoRA fused linear:  y = x @ W + (1/R) * (x @ A[l]) @ B[l] + bias
//   x: [T,D] f32, labels: [T] i32/i64, W: [D,D] f32, A: [E,D,R] f32,
//   B: [E,R,D] f32, bias: [D] f32, out: [T,D] f32.  T=16384 D=1024 R=8 E=64
//
// Round 14 = Round 13 + fp16 A-gather in convert_x_xa (halves the 512 MB
// per-token A traffic that dominates the auxiliary 115 us).
// GEMM kernel unchanged (best known: 64x32 warp tiles, 16 warps, all-resident
// fragments, fp16-B epilogue).
// ===========================================================================

#define D_DIM 1024
#define R_DIM 8
#define SCALING 0.125f
#define MAX_T 16384
#define E_DIM 64

#define BM 256
#define BN 128
#define BKB 64                        // fp16 K per chunk
#define NSTAGE 4
#define NCHUNK 16                     // 1024 / 64
#define ROWSTRIDE 72                  // fp16 per smem row (64 + 8 pad) = 144 B
#define APLANE_BYTES (256 * ROWSTRIDE * 2)    // 36864 (x: 256 rows)
#define BPLANE_BYTES (128 * ROWSTRIDE * 2)    // 18432 (w: 128 rows)
#define OFF_X 0
#define OFF_W (APLANE_BYTES)
#define STAGE_BYTES (APLANE_BYTES + BPLANE_BYTES)   // 55296
#define SMEM_BYTES (NSTAGE * STAGE_BYTES)           // 221184

// -------------------- device-global scratch (no allocs allowed) ------------
__device__ __align__(256) unsigned short g_x16[MAX_T * D_DIM];   // x fp16
__device__ __align__(256) unsigned short g_w16[D_DIM * D_DIM];   // W^T fp16
__device__ __align__(256) unsigned short g_b16[E_DIM * R_DIM * D_DIM]; // B fp16
__device__ __align__(256) unsigned short g_a16[E_DIM * D_DIM * R_DIM]; // A fp16
__device__ __align__(16)  float          g_xa[MAX_T * R_DIM];
__device__ int g_lab64;

// ------------------------------ helpers ------------------------------------
__device__ __forceinline__ uint32_t smem_u32(const void* p) {
    uint32_t a;
    asm("{ .reg .u64 t; cvta.to.shared.u64 t, %1; cvt.u32.u64 %0, t; }"
        : "=r"(a) : "l"(p));
    return a;
}
#define CP_ASYNC16(dst, src) \
    asm volatile("cp.async.cg.shared.global [%0], [%1], 16;" \
                 :: "r"(dst), "l"(src) : "memory")
#define CP_COMMIT() asm volatile("cp.async.commit_group;" ::: "memory")
#define CP_WAIT2()  asm volatile("cp.async.wait_group 2;" ::: "memory")
#define CP_WAIT0()  asm volatile("cp.async.wait_group 0;" ::: "memory")

#define LDSM4(r0, r1, r2, r3, addr) \
    asm volatile("ldmatrix.sync.aligned.m8n8.x4.shared.b16 {%0,%1,%2,%3}, [%4];" \
                 : "=r"(r0), "=r"(r1), "=r"(r2), "=r"(r3) : "r"(addr))

#define MMA16816F16(c, a, b) \
    asm volatile("mma.sync.aligned.m16n8k16.row.col.f32.f16.f16.f32 " \
                 "{%0,%1,%2,%3}, {%4,%5,%6,%7}, {%8,%9}, {%0,%1,%2,%3};" \
                 : "+f"((c)[0]), "+f"((c)[1]), "+f"((c)[2]), "+f"((c)[3]) \
                 : "r"((a)[0]), "r"((a)[1]), "r"((a)[2]), "r"((a)[3]), \
                   "r"((b)[0]), "r"((b)[1]))

// ---------------------------------------------------------------------------
// Kernel 0: classify labels dtype (int64 vs int32) deterministically.
// ---------------------------------------------------------------------------
__global__ void detect_label_dtype_kernel(const void* labels, int T) {
    if (threadIdx.x != 0 || blockIdx.x != 0) return;
    const long long* p = (const long long*)labels;
    int n = T < 256 ? T : 256;
    int is64 = 1;
    for (int i = 0; i < n; ++i) {
        long long v = p[i];
        if (v < 0 || v >= (1LL << 31)) { is64 = 0; break; }
    }
    g_lab64 = is64;
}
__device__ __forceinline__ int load_label(const void* labels, int t) {
    if (g_lab64) return (int)((const long long*)labels)[t];
    return ((const int*)labels)[t];
}

// ---------------------------------------------------------------------------
// Kernel 0b: convert A and B to fp16 (both 512K floats).
// ---------------------------------------------------------------------------
__global__ void __launch_bounds__(256)
convert_ab_kernel(const float* __restrict__ A, const float* __restrict__ B,
                  int nA4, int nTot4) {
    int i = blockIdx.x * 256 + threadIdx.x;
    if (i >= nTot4) return;
    const float4 v = (i < nA4) ? ((const float4*)A)[i]
                               : ((const float4*)B)[i - nA4];
    __half2 h01 = __floats2half2_rn(v.x, v.y);
    __half2 h23 = __floats2half2_rn(v.z, v.w);
    uint2 o;
    o.x = *(uint32_t*)&h01;
    o.y = *(uint32_t*)&h23;
    if (i < nA4) ((uint2*)g_a16)[i] = o;
    else         ((uint2*)g_b16)[i - nA4] = o;
}

// ---------------------------------------------------------------------------
// Kernel 1: fused  x -> fp16  +  xa = x . A16[label]   (one warp per token)
// A gathered as fp16: one uint4 per [d, 0:8] row -> half the L2 traffic.
// ---------------------------------------------------------------------------
__global__ void __launch_bounds__(256)
convert_x_xa_kernel(const float* __restrict__ x,
                    const void*  __restrict__ labels, int T) {
    int t = blockIdx.x * 8 + (threadIdx.x >> 5);
    if (t >= T) return;
    const int lane = threadIdx.x & 31;
    const int e = load_label(labels, t);
    const float* xrow = x + (size_t)t * D_DIM;
    const unsigned short* Ae = g_a16 + (size_t)e * D_DIM * R_DIM;
    unsigned short* xo = g_x16 + (size_t)t * D_DIM;

    float acc[R_DIM];
#pragma unroll
    for (int r = 0; r < R_DIM; ++r) acc[r] = 0.0f;

#pragma unroll
    for (int i = 0; i < 8; ++i) {
        const int d = i * 128 + lane * 4;
        float4 v = *(const float4*)(xrow + d);
        float vv[4] = {v.x, v.y, v.z, v.w};

        ushort4 h4;
        __half h;
        h = __float2half_rn(vv[0]); h4.x = *(unsigned short*)&h;
        h = __float2half_rn(vv[1]); h4.y = *(unsigned short*)&h;
        h = __float2half_rn(vv[2]); h4.z = *(unsigned short*)&h;
        h = __float2half_rn(vv[3]); h4.w = *(unsigned short*)&h;
        *(ushort4*)(xo + d) = h4;

#pragma unroll
        for (int j = 0; j < 4; ++j) {
            uint4 q = *(const uint4*)(Ae + (size_t)(d + j) * R_DIM);
            float2 f0 = __half22float2(*(__half2*)&q.x);
            float2 f1 = __half22float2(*(__half2*)&q.y);
            float2 f2 = __half22float2(*(__half2*)&q.z);
            float2 f3 = __half22float2(*(__half2*)&q.w);
            float xv = vv[j];
            acc[0] += xv * f0.x;  acc[1] += xv * f0.y;
            acc[2] += xv * f1.x;  acc[3] += xv * f1.y;
            acc[4] += xv * f2.x;  acc[5] += xv * f2.y;
            acc[6] += xv * f3.x;  acc[7] += xv * f3.y;
        }
    }
#pragma unroll
    for (int off = 16; off > 0; off >>= 1)
#pragma unroll
        for (int r = 0; r < R_DIM; ++r)
            acc[r] += __shfl_down_sync(0xffffffffu, acc[r], off);
    if (lane == 0) {
        float4* o = (float4*)(g_xa + (size_t)t * R_DIM);
        o[0] = make_float4(acc[0], acc[1], acc[2], acc[3]);
        o[1] = make_float4(acc[4], acc[5], acc[6], acc[7]);
    }
}

// ---------------------------------------------------------------------------
// Kernel 2: Wt[n][k] = fp16(W[k][n])
// ---------------------------------------------------------------------------
__global__ void __launch_bounds__(256)
convert_w_kernel(const float* __restrict__ W) {
    __shared__ float s[32][33];
    const int k0 = blockIdx.x * 32;
    const int n0 = blockIdx.y * 32;
    const int tx = threadIdx.x & 31;
    const int ty = threadIdx.x >> 5;
#pragma unroll
    for (int r = 0; r < 4; ++r) {
        int kk = ty + r * 8;
        s[kk][tx] = W[(size_t)(k0 + kk) * D_DIM + n0 + tx];
    }
    __syncthreads();
#pragma unroll
    for (int r = 0; r < 4; ++r) {
        int nn = ty + r * 8;
        __half h = __float2half_rn(s[tx][nn]);
        g_w16[(size_t)(n0 + nn) * D_DIM + k0 + tx] = *(unsigned short*)&h;
    }
}

// ---------------------------------------------------------------------------
// Kernel 3: fp16 GEMM + fused LoRA/bias epilogue.  (unchanged from round 13)
//   512 threads = 16 warps (4M x 4N), warp tile 64x32, BM=256 BN=128.
//   Per ks: 6 LDSM4 (all fragments resident) -> 16 independent MMAs.
// ---------------------------------------------------------------------------
__global__ void __launch_bounds__(512, 1)
gemm_lora_kernel(const void*  __restrict__ labels,
                 const float* __restrict__ bias,
                 float* __restrict__ out) {
    extern __shared__ char smem[];
    const uint32_t sbase = smem_u32(smem);
    const int tid  = threadIdx.x;
    const int row0 = blockIdx.y * BM;
    const int col0 = blockIdx.x * BN;

    const int warp = tid >> 5, lane = tid & 31;
    const int wm = warp >> 2, wn = warp & 3;
    const uint32_t a_lm_base =
        (uint32_t)((wm * 64 + (lane & 15)) * ROWSTRIDE + (lane >> 4) * 8) * 2;
    const uint32_t b_lm_base =
        (uint32_t)((wn * 32 + (lane >> 4) * 8 + (lane & 7)) * ROWSTRIDE +
                   ((lane >> 3) & 1) * 8) * 2;

    float c[4][4][4];                 // 64 accumulators
#pragma unroll
    for (int i = 0; i < 4; ++i)
#pragma unroll
        for (int j = 0; j < 4; ++j)
#pragma unroll
            for (int q = 0; q < 4; ++q) c[i][j][q] = 0.0f;

    auto issue = [&](int cn) {
        const int kk = cn * BKB;
        const uint32_t sa = sbase + (uint32_t)(cn % NSTAGE) * STAGE_BYTES;
#pragma unroll
        for (int i = 0; i < 4; ++i) {
            const int idx = tid + i * 512;
            const int r = idx >> 3, s = idx & 7;
            CP_ASYNC16(sa + OFF_X + (uint32_t)(r * (ROWSTRIDE * 2) + s * 16),
                       g_x16 + (size_t)(row0 + r) * D_DIM + kk + s * 8);
        }
#pragma unroll
        for (int i = 0; i < 2; ++i) {
            const int idx = tid + i * 512;
            const int r = idx >> 3, s = idx & 7;
            CP_ASYNC16(sa + OFF_W + (uint32_t)(r * (ROWSTRIDE * 2) + s * 16),
                       g_w16 + (size_t)(col0 + r) * D_DIM + kk + s * 8);
        }
    };

#pragma unroll
    for (int cn = 0; cn < 3; ++cn) { issue(cn); CP_COMMIT(); }

    for (int ch = 0; ch < NCHUNK; ++ch) {
        CP_WAIT2();
        __syncthreads();

        if (ch + 3 < NCHUNK) { issue(ch + 3); }
        CP_COMMIT();

        const uint32_t sa = sbase + (uint32_t)(ch % NSTAGE) * STAGE_BYTES;

#pragma unroll
        for (int ks = 0; ks < 4; ++ks) {
            uint32_t bfr[4][2];
#pragma unroll
            for (int p = 0; p < 2; ++p) {
                uint32_t bo = b_lm_base + (uint32_t)(p * 16 * ROWSTRIDE + ks * 16) * 2;
                uint32_t r0, r1, r2, r3;
                LDSM4(r0, r1, r2, r3, sa + OFF_W + bo);
                bfr[2 * p][0] = r0;      bfr[2 * p][1] = r1;
                bfr[2 * p + 1][0] = r2;  bfr[2 * p + 1][1] = r3;
            }
            uint32_t afr[4][4];
#pragma unroll
            for (int mf = 0; mf < 4; ++mf) {
                uint32_t ao = a_lm_base + (uint32_t)(mf * 16 * ROWSTRIDE + ks * 16) * 2;
                LDSM4(afr[mf][0], afr[mf][1], afr[mf][2], afr[mf][3], sa + OFF_X + ao);
            }
#pragma unroll
            for (int mf = 0; mf < 4; ++mf)
#pragma unroll
                for (int nf = 0; nf < 4; ++nf)
                    MMA16816F16(c[mf][nf], afr[mf], bfr[nf]);
        }
    }
    CP_WAIT0();
    __syncthreads();

    // ---- stage accumulators to smem (reuse pipeline smem) ----
    float* acc_s = (float*)smem;                 // [256][132] = 135 KB
    const int g = lane >> 2, q = lane & 3;
#pragma unroll
    for (int mf = 0; mf < 4; ++mf) {
        const int r1 = wm * 64 + mf * 16 + g;
#pragma unroll
        for (int nf = 0; nf < 4; ++nf) {
            const int cc = wn * 32 + nf * 8 + q * 2;
            *(float2*)&acc_s[r1 * 132 + cc]       = make_float2(c[mf][nf][0], c[mf][nf][1]);
            *(float2*)&acc_s[(r1 + 8) * 132 + cc] = make_float2(c[mf][nf][2], c[mf][nf][3]);
        }
    }
    __syncthreads();

    // ---- epilogue: per-token rank-8 LoRA (fp16 B) + bias ----
    const int lr   = tid >> 1;           // 0..255
    const int half = (tid & 1) * 64;     // column half
    const int t    = row0 + lr;
    const int e    = load_label(labels, t);

    float xs[R_DIM];
    {
        const float4* p = (const float4*)(g_xa + (size_t)t * R_DIM);
        float4 a0 = p[0], a1 = p[1];
        xs[0] = SCALING * a0.x; xs[1] = SCALING * a0.y;
        xs[2] = SCALING * a0.z; xs[3] = SCALING * a0.w;
        xs[4] = SCALING * a1.x; xs[5] = SCALING * a1.y;
        xs[6] = SCALING * a1.z; xs[7] = SCALING * a1.w;
    }

    const unsigned short* Be = g_b16 + (size_t)e * R_DIM * D_DIM + col0 + half;
    float*       orow = out  + (size_t)t * D_DIM + col0 + half;
    const float* brow = bias + col0 + half;

#pragma unroll
    for (int part = 0; part < 2; ++part) {
        const int pc = part * 32;
        float res[32];
#pragma unroll
        for (int v = 0; v < 8; ++v)
            *(float4*)&res[v * 4] = *(const float4*)&acc_s[lr * 132 + half + pc + v * 4];

#pragma unroll
        for (int r = 0; r < R_DIM; ++r) {
            const uint4* bp = (const uint4*)(Be + (size_t)r * D_DIM + pc);
            const float xr = xs[r];
#pragma unroll
            for (int v = 0; v < 4; ++v) {
                uint4 q4 = bp[v];
                float2 f0 = __half22float2(*(__half2*)&q4.x);
                float2 f1 = __half22float2(*(__half2*)&q4.y);
                float2 f2 = __half22float2(*(__half2*)&q4.z);
                float2 f3 = __half22float2(*(__half2*)&q4.w);
                res[v * 8 + 0] += xr * f0.x;  res[v * 8 + 1] += xr * f0.y;
                res[v * 8 + 2] += xr * f1.x;  res[v * 8 + 3] += xr * f1.y;
                res[v * 8 + 4] += xr * f2.x;  res[v * 8 + 5] += xr * f2.y;
                res[v * 8 + 6] += xr * f3.x;  res[v * 8 + 7] += xr * f3.y;
            }
        }
        const float4* bi = (const float4*)(brow + pc);
#pragma unroll
        for (int v = 0; v < 8; ++v) {
            float4 bv = bi[v];
            float4 o4 = make_float4(res[v * 4 + 0] + bv.x, res[v * 4 + 1] + bv.y,
                                    res[v * 4 + 2] + bv.z, res[v * 4 + 3] + bv.w);
            ((float4*)(orow + pc))[v] = o4;
        }
    }
}

// ---------------------------------------------------------------------------
// kernel_launch — graph-capturable, allocation-free.
// Inputs: x, labels, W, A, B, bias
// ---------------------------------------------------------------------------
extern "C" void kernel_launch(void* const* d_in, const int* in_sizes, int n_in,
                              void* d_out, int out_size) {
    const float* x      = (const float*)d_in[0];
    const void*  labels = (const void*) d_in[1];
    const float* W      = (const float*)d_in[2];
    const float* A      = (const float*)d_in[3];
    const float* B      = (const float*)d_in[4];
    const float* bias   = (const float*)d_in[5];
    float* out          = (float*)d_out;

    const int T = in_sizes[0] / D_DIM;

    detect_label_dtype_kernel<<<1, 32>>>(labels, T);

    const int nA4 = E_DIM * D_DIM * R_DIM / 4;      // 128K
    const int nB4 = E_DIM * R_DIM * D_DIM / 4;      // 128K
    convert_ab_kernel<<<(nA4 + nB4 + 255) / 256, 256>>>(A, B, nA4, nA4 + nB4);

    convert_x_xa_kernel<<<(T + 7) / 8, 256>>>(x, labels, T);
    convert_w_kernel<<<dim3(D_DIM / 32, D_DIM / 32), 256>>>(W);

    static int smem_set = 0;
    if (!smem_set) {
        cudaFuncSetAttribute(gemm_lora_kernel,
                             cudaFuncAttributeMaxDynamicSharedMemorySize, SMEM_BYTES);
        smem_set = 1;
    }
    dim3 grid(D_DIM / BN, T / BM);
    gemm_lora_kernel<<<grid, 512, SMEM_BYTES>>>(labels, bias, out);
}

// round 15
// speedup vs baseline: 2.0339x; 1.0242x over previous
#include <cuda_runtime.h>
#include <cuda_fp16.h>
#include <stdint.h>

// ===========================================================================
// MoE-LoRA fused linear:  y = x @ W + (1/R) * (x @ A[l]) @ B[l] + bias
//   x: [T,D] f32, labels: [T] i32/i64, W: [D,D] f32, A: [E,D,R] f32,
//   B: [E,R,D] f32, bias: [D] f32, out: [T,D] f32.  T=16384 D=1024 R=8 E=64
//
// Round 15 = Round 14 with the aux chain consolidated:
//   - ONE prep kernel: label-dtype detect (warp-parallel) + A->fp16 +
//     B->fp16 + W^T->fp16 (was 3 launches incl. a 4 us serial detect).
//   - GEMM kernel frozen (near legacy-HMMA roofline); epilogue out-stores
//     use streaming hint (__stcs) to keep L2 for B/x reuse.
// ===========================================================================

#define D_DIM 1024
#define R_DIM 8
#define SCALING 0.125f
#define MAX_T 16384
#define E_DIM 64

#define BM 256
#define BN 128
#define BKB 64                        // fp16 K per chunk
#define NSTAGE 4
#define NCHUNK 16                     // 1024 / 64
#define ROWSTRIDE 72                  // fp16 per smem row (64 + 8 pad) = 144 B
#define APLANE_BYTES (256 * ROWSTRIDE * 2)    // 36864 (x: 256 rows)
#define BPLANE_BYTES (128 * ROWSTRIDE * 2)    // 18432 (w: 128 rows)
#define OFF_X 0
#define OFF_W (APLANE_BYTES)
#define STAGE_BYTES (APLANE_BYTES + BPLANE_BYTES)   // 55296
#define SMEM_BYTES (NSTAGE * STAGE_BYTES)           // 221184

// -------------------- device-global scratch (no allocs allowed) ------------
__device__ __align__(256) unsigned short g_x16[MAX_T * D_DIM];   // x fp16
__device__ __align__(256) unsigned short g_w16[D_DIM * D_DIM];   // W^T fp16
__device__ __align__(256) unsigned short g_b16[E_DIM * R_DIM * D_DIM]; // B fp16
__device__ __align__(256) unsigned short g_a16[E_DIM * D_DIM * R_DIM]; // A fp16
__device__ __align__(16)  float          g_xa[MAX_T * R_DIM];
__device__ int g_lab64;

// ------------------------------ helpers ------------------------------------
__device__ __forceinline__ uint32_t smem_u32(const void* p) {
    uint32_t a;
    asm("{ .reg .u64 t; cvta.to.shared.u64 t, %1; cvt.u32.u64 %0, t; }"
        : "=r"(a) : "l"(p));
    return a;
}
#define CP_ASYNC16(dst, src) \
    asm volatile("cp.async.cg.shared.global [%0], [%1], 16;" \
                 :: "r"(dst), "l"(src) : "memory")
#define CP_COMMIT() asm volatile("cp.async.commit_group;" ::: "memory")
#define CP_WAIT2()  asm volatile("cp.async.wait_group 2;" ::: "memory")
#define CP_WAIT0()  asm volatile("cp.async.wait_group 0;" ::: "memory")

#define LDSM4(r0, r1, r2, r3, addr) \
    asm volatile("ldmatrix.sync.aligned.m8n8.x4.shared.b16 {%0,%1,%2,%3}, [%4];" \
                 : "=r"(r0), "=r"(r1), "=r"(r2), "=r"(r3) : "r"(addr))

#define MMA16816F16(c, a, b) \
    asm volatile("mma.sync.aligned.m16n8k16.row.col.f32.f16.f16.f32 " \
                 "{%0,%1,%2,%3}, {%4,%5,%6,%7}, {%8,%9}, {%0,%1,%2,%3};" \
                 : "+f"((c)[0]), "+f"((c)[1]), "+f"((c)[2]), "+f"((c)[3]) \
                 : "r"((a)[0]), "r"((a)[1]), "r"((a)[2]), "r"((a)[3]), \
                   "r"((b)[0]), "r"((b)[1]))

__device__ __forceinline__ int load_label_dyn(const void* labels, int t) {
    if (g_lab64) return (int)((const long long*)labels)[t];
    return ((const int*)labels)[t];
}

// ---------------------------------------------------------------------------
// Kernel 0 (fused prep): blocks [0,1024) convert A+B -> fp16;
// blocks [1024,2048) transpose+convert W -> fp16; block 2048 detects the
// labels dtype with a warp-parallel scan.
// ---------------------------------------------------------------------------
__global__ void __launch_bounds__(256)
prep_kernel(const float* __restrict__ A, const float* __restrict__ B,
            const float* __restrict__ W, const void* __restrict__ labels,
            int T) {
    const int b = blockIdx.x;

    if (b < 1024) {
        // ---- A/B elementwise fp16 convert (256K float4 total) ----
        const int nA4 = E_DIM * D_DIM * R_DIM / 4;   // 128K
        int i = b * 256 + threadIdx.x;
        const float4 v = (i < nA4) ? ((const float4*)A)[i]
                                   : ((const float4*)B)[i - nA4];
        __half2 h01 = __floats2half2_rn(v.x, v.y);
        __half2 h23 = __floats2half2_rn(v.z, v.w);
        uint2 o;
        o.x = *(uint32_t*)&h01;
        o.y = *(uint32_t*)&h23;
        if (i < nA4) ((uint2*)g_a16)[i] = o;
        else         ((uint2*)g_b16)[i - nA4] = o;
        return;
    }
    if (b < 2048) {
        // ---- W transpose + fp16 convert: 32x32 tile per block ----
        __shared__ float s[32][33];
        const int wid = b - 1024;
        const int k0 = (wid & 31) * 32;
        const int n0 = (wid >> 5) * 32;
        const int tx = threadIdx.x & 31;
        const int ty = threadIdx.x >> 5;
#pragma unroll
        for (int r = 0; r < 4; ++r) {
            int kk = ty + r * 8;
            s[kk][tx] = W[(size_t)(k0 + kk) * D_DIM + n0 + tx];
        }
        __syncthreads();
#pragma unroll
        for (int r = 0; r < 4; ++r) {
            int nn = ty + r * 8;
            __half h = __float2half_rn(s[tx][nn]);
            g_w16[(size_t)(n0 + nn) * D_DIM + k0 + tx] = *(unsigned short*)&h;
        }
        return;
    }
    // ---- label dtype detect: warp-parallel over 256 int64 probes ----
    if (threadIdx.x < 32) {
        const long long* p = (const long long*)labels;
        int n = T < 256 ? T : 256;
        int bad = 0;
        for (int i = threadIdx.x; i < n; i += 32) {
            long long v = p[i];
            if (v < 0 || v >= (1LL << 31)) bad = 1;
        }
        unsigned any_bad = __ballot_sync(0xffffffffu, bad);
        if (threadIdx.x == 0) g_lab64 = (any_bad == 0u) ? 1 : 0;
    }
}

// ---------------------------------------------------------------------------
// Kernel 1: fused  x -> fp16  +  xa = x . A16[label]   (one warp per token)
// ---------------------------------------------------------------------------
__global__ void __launch_bounds__(256)
convert_x_xa_kernel(const float* __restrict__ x,
                    const void*  __restrict__ labels, int T) {
    int t = blockIdx.x * 8 + (threadIdx.x >> 5);
    if (t >= T) return;
    const int lane = threadIdx.x & 31;
    const int e = load_label_dyn(labels, t);
    const float* xrow = x + (size_t)t * D_DIM;
    const unsigned short* Ae = g_a16 + (size_t)e * D_DIM * R_DIM;
    unsigned short* xo = g_x16 + (size_t)t * D_DIM;

    float acc[R_DIM];
#pragma unroll
    for (int r = 0; r < R_DIM; ++r) acc[r] = 0.0f;

#pragma unroll
    for (int i = 0; i < 8; ++i) {
        const int d = i * 128 + lane * 4;
        float4 v = *(const float4*)(xrow + d);
        float vv[4] = {v.x, v.y, v.z, v.w};

        ushort4 h4;
        __half h;
        h = __float2half_rn(vv[0]); h4.x = *(unsigned short*)&h;
        h = __float2half_rn(vv[1]); h4.y = *(unsigned short*)&h;
        h = __float2half_rn(vv[2]); h4.z = *(unsigned short*)&h;
        h = __float2half_rn(vv[3]); h4.w = *(unsigned short*)&h;
        *(ushort4*)(xo + d) = h4;

#pragma unroll
        for (int j = 0; j < 4; ++j) {
            uint4 q = *(const uint4*)(Ae + (size_t)(d + j) * R_DIM);
            float2 f0 = __half22float2(*(__half2*)&q.x);
            float2 f1 = __half22float2(*(__half2*)&q.y);
            float2 f2 = __half22float2(*(__half2*)&q.z);
            float2 f3 = __half22float2(*(__half2*)&q.w);
            float xv = vv[j];
            acc[0] += xv * f0.x;  acc[1] += xv * f0.y;
            acc[2] += xv * f1.x;  acc[3] += xv * f1.y;
            acc[4] += xv * f2.x;  acc[5] += xv * f2.y;
            acc[6] += xv * f3.x;  acc[7] += xv * f3.y;
        }
    }
#pragma unroll
    for (int off = 16; off > 0; off >>= 1)
#pragma unroll
        for (int r = 0; r < R_DIM; ++r)
            acc[r] += __shfl_down_sync(0xffffffffu, acc[r], off);
    if (lane == 0) {
        float4* o = (float4*)(g_xa + (size_t)t * R_DIM);
        o[0] = make_float4(acc[0], acc[1], acc[2], acc[3]);
        o[1] = make_float4(acc[4], acc[5], acc[6], acc[7]);
    }
}

// ---------------------------------------------------------------------------
// Kernel 2: fp16 GEMM + fused LoRA/bias epilogue.  (frozen from round 13/14)
//   512 threads = 16 warps (4M x 4N), warp tile 64x32, BM=256 BN=128.
// ---------------------------------------------------------------------------
__global__ void __launch_bounds__(512, 1)
gemm_lora_kernel(const void*  __restrict__ labels,
                 const float* __restrict__ bias,
                 float* __restrict__ out) {
    extern __shared__ char smem[];
    const uint32_t sbase = smem_u32(smem);
    const int tid  = threadIdx.x;
    const int row0 = blockIdx.y * BM;
    const int col0 = blockIdx.x * BN;

    const int warp = tid >> 5, lane = tid & 31;
    const int wm = warp >> 2, wn = warp & 3;
    const uint32_t a_lm_base =
        (uint32_t)((wm * 64 + (lane & 15)) * ROWSTRIDE + (lane >> 4) * 8) * 2;
    const uint32_t b_lm_base =
        (uint32_t)((wn * 32 + (lane >> 4) * 8 + (lane & 7)) * ROWSTRIDE +
                   ((lane >> 3) & 1) * 8) * 2;

    float c[4][4][4];                 // 64 accumulators
#pragma unroll
    for (int i = 0; i < 4; ++i)
#pragma unroll
        for (int j = 0; j < 4; ++j)
#pragma unroll
            for (int q = 0; q < 4; ++q) c[i][j][q] = 0.0f;

    auto issue = [&](int cn) {
        const int kk = cn * BKB;
        const uint32_t sa = sbase + (uint32_t)(cn % NSTAGE) * STAGE_BYTES;
#pragma unroll
        for (int i = 0; i < 4; ++i) {
            const int idx = tid + i * 512;
            const int r = idx >> 3, s = idx & 7;
            CP_ASYNC16(sa + OFF_X + (uint32_t)(r * (ROWSTRIDE * 2) + s * 16),
                       g_x16 + (size_t)(row0 + r) * D_DIM + kk + s * 8);
        }
#pragma unroll
        for (int i = 0; i < 2; ++i) {
            const int idx = tid + i * 512;
            const int r = idx >> 3, s = idx & 7;
            CP_ASYNC16(sa + OFF_W + (uint32_t)(r * (ROWSTRIDE * 2) + s * 16),
                       g_w16 + (size_t)(col0 + r) * D_DIM + kk + s * 8);
        }
    };

#pragma unroll
    for (int cn = 0; cn < 3; ++cn) { issue(cn); CP_COMMIT(); }

    for (int ch = 0; ch < NCHUNK; ++ch) {
        CP_WAIT2();
        __syncthreads();

        if (ch + 3 < NCHUNK) { issue(ch + 3); }
        CP_COMMIT();

        const uint32_t sa = sbase + (uint32_t)(ch % NSTAGE) * STAGE_BYTES;

#pragma unroll
        for (int ks = 0; ks < 4; ++ks) {
            uint32_t bfr[4][2];
#pragma unroll
            for (int p = 0; p < 2; ++p) {
                uint32_t bo = b_lm_base + (uint32_t)(p * 16 * ROWSTRIDE + ks * 16) * 2;
                uint32_t r0, r1, r2, r3;
                LDSM4(r0, r1, r2, r3, sa + OFF_W + bo);
                bfr[2 * p][0] = r0;      bfr[2 * p][1] = r1;
                bfr[2 * p + 1][0] = r2;  bfr[2 * p + 1][1] = r3;
            }
            uint32_t afr[4][4];
#pragma unroll
            for (int mf = 0; mf < 4; ++mf) {
                uint32_t ao = a_lm_base + (uint32_t)(mf * 16 * ROWSTRIDE + ks * 16) * 2;
                LDSM4(afr[mf][0], afr[mf][1], afr[mf][2], afr[mf][3], sa + OFF_X + ao);
            }
#pragma unroll
            for (int mf = 0; mf < 4; ++mf)
#pragma unroll
                for (int nf = 0; nf < 4; ++nf)
                    MMA16816F16(c[mf][nf], afr[mf], bfr[nf]);
        }
    }
    CP_WAIT0();
    __syncthreads();

    // ---- stage accumulators to smem (reuse pipeline smem) ----
    float* acc_s = (float*)smem;                 // [256][132] = 135 KB
    const int g = lane >> 2, q = lane & 3;
#pragma unroll
    for (int mf = 0; mf < 4; ++mf) {
        const int r1 = wm * 64 + mf * 16 + g;
#pragma unroll
        for (int nf = 0; nf < 4; ++nf) {
            const int cc = wn * 32 + nf * 8 + q * 2;
            *(float2*)&acc_s[r1 * 132 + cc]       = make_float2(c[mf][nf][0], c[mf][nf][1]);
            *(float2*)&acc_s[(r1 + 8) * 132 + cc] = make_float2(c[mf][nf][2], c[mf][nf][3]);
        }
    }
    __syncthreads();

    // ---- epilogue: per-token rank-8 LoRA (fp16 B) + bias ----
    const int lr   = tid >> 1;           // 0..255
    const int half = (tid & 1) * 64;     // column half
    const int t    = row0 + lr;
    const int e    = load_label_dyn(labels, t);

    float xs[R_DIM];
    {
        const float4* p = (const float4*)(g_xa + (size_t)t * R_DIM);
        float4 a0 = p[0], a1 = p[1];
        xs[0] = SCALING * a0.x; xs[1] = SCALING * a0.y;
        xs[2] = SCALING * a0.z; xs[3] = SCALING * a0.w;
        xs[4] = SCALING * a1.x; xs[5] = SCALING * a1.y;
        xs[6] = SCALING * a1.z; xs[7] = SCALING * a1.w;
    }

    const unsigned short* Be = g_b16 + (size_t)e * R_DIM * D_DIM + col0 + half;
    float*       orow = out  + (size_t)t * D_DIM + col0 + half;
    const float* brow = bias + col0 + half;

#pragma unroll
    for (int part = 0; part < 2; ++part) {
        const int pc = part * 32;
        float res[32];
#pragma unroll
        for (int v = 0; v < 8; ++v)
            *(float4*)&res[v * 4] = *(const float4*)&acc_s[lr * 132 + half + pc + v * 4];

#pragma unroll
        for (int r = 0; r < R_DIM; ++r) {
            const uint4* bp = (const uint4*)(Be + (size_t)r * D_DIM + pc);
            const float xr = xs[r];
#pragma unroll
            for (int v = 0; v < 4; ++v) {
                uint4 q4 = bp[v];
                float2 f0 = __half22float2(*(__half2*)&q4.x);
                float2 f1 = __half22float2(*(__half2*)&q4.y);
                float2 f2 = __half22float2(*(__half2*)&q4.z);
                float2 f3 = __half22float2(*(__half2*)&q4.w);
                res[v * 8 + 0] += xr * f0.x;  res[v * 8 + 1] += xr * f0.y;
                res[v * 8 + 2] += xr * f1.x;  res[v * 8 + 3] += xr * f1.y;
                res[v * 8 + 4] += xr * f2.x;  res[v * 8 + 5] += xr * f2.y;
                res[v * 8 + 6] += xr * f3.x;  res[v * 8 + 7] += xr * f3.y;
            }
        }
        const float4* bi = (const float4*)(brow + pc);
#pragma unroll
        for (int v = 0; v < 8; ++v) {
            float4 bv = bi[v];
            float4 o4 = make_float4(res[v * 4 + 0] + bv.x, res[v * 4 + 1] + bv.y,
                                    res[v * 4 + 2] + bv.z, res[v * 4 + 3] + bv.w);
            __stcs((float4*)(orow + pc) + v, o4);   // streaming store
        }
    }
}

// ---------------------------------------------------------------------------
// kernel_launch — graph-capturable, allocation-free.
// Inputs: x, labels, W, A, B, bias
// ---------------------------------------------------------------------------
extern "C" void kernel_launch(void* const* d_in, const int* in_sizes, int n_in,
                              void* d_out, int out_size) {
    const float* x      = (const float*)d_in[0];
    const void*  labels = (const void*) d_in[1];
    const float* W      = (const float*)d_in[2];
    const float* A      = (const float*)d_in[3];
    const float* B      = (const float*)d_in[4];
    const float* bias   = (const float*)d_in[5];
    float* out          = (float*)d_out;

    const int T = in_sizes[0] / D_DIM;

    // One fused prep launch: A/B/W fp16 conversion + label dtype detect.
    prep_kernel<<<2049, 256>>>(A, B, W, labels, T);

    convert_x_xa_kernel<<<(T + 7) / 8, 256>>>(x, labels, T);

    static int smem_set = 0;
    if (!smem_set) {
        cudaFuncSetAttribute(gemm_lora_kernel,
                             cudaFuncAttributeMaxDynamicSharedMemorySize, SMEM_BYTES);
        smem_set = 1;
    }
    dim3 grid(D_DIM / BN, T / BM);
    gemm_lora_kernel<<<grid, 512, SMEM_BYTES>>>(labels, bias, out);
}

// round 16
// speedup vs baseline: 2.2445x; 1.1035x over previous
#include <cuda_runtime.h>
#include <cuda_fp16.h>
#include <stdint.h>

// ===========================================================================
// MoE-LoRA fused linear:  y = x @ W + (1/R) * (x @ A[l]) @ B[l] + bias
//   x: [T,D] f32, labels: [T] i32/i64, W: [D,D] f32, A: [E,D,R] f32,
//   B: [E,R,D] f32, bias: [D] f32, out: [T,D] f32.  T=16384 D=1024 R=8 E=64
//
// Round 16 = Round 15 + expert-sorted token order:
//   counting sort (hist/scan/scatter, ~5us) makes every thread block
//   expert-coherent, so A (convert_x_xa) and B (GEMM epilogue) become
//   L1-resident instead of 256 MB L2 streams each.
//   GEMM rows indirect through g_sorted (gathered loads, scattered stores).
// ===========================================================================

#define D_DIM 1024
#define R_DIM 8
#define SCALING 0.125f
#define MAX_T 16384
#define E_DIM 64

#define BM 256
#define BN 128
#define BKB 64                        // fp16 K per chunk
#define NSTAGE 4
#define NCHUNK 16                     // 1024 / 64
#define ROWSTRIDE 72                  // fp16 per smem row (64 + 8 pad) = 144 B
#define APLANE_BYTES (256 * ROWSTRIDE * 2)    // 36864 (x: 256 rows)
#define BPLANE_BYTES (128 * ROWSTRIDE * 2)    // 18432 (w: 128 rows)
#define OFF_X 0
#define OFF_W (APLANE_BYTES)
#define STAGE_BYTES (APLANE_BYTES + BPLANE_BYTES)   // 55296
#define TOKMAP_OFF (NSTAGE * STAGE_BYTES)           // 221184
#define SMEM_BYTES (TOKMAP_OFF + 256 * 4)           // 222208

// -------------------- device-global scratch (no allocs allowed) ------------
__device__ __align__(256) unsigned short g_x16[MAX_T * D_DIM];   // x fp16
__device__ __align__(256) unsigned short g_w16[D_DIM * D_DIM];   // W^T fp16
__device__ __align__(256) unsigned short g_b16[E_DIM * R_DIM * D_DIM]; // B fp16
__device__ __align__(256) unsigned short g_a16[E_DIM * D_DIM * R_DIM]; // A fp16
__device__ __align__(16)  float          g_xa[MAX_T * R_DIM];
__device__ int g_sorted[MAX_T];
__device__ int g_hist[E_DIM];
__device__ int g_off[E_DIM];
__device__ int g_fill[E_DIM];
__device__ int g_lab64;

// ------------------------------ helpers ------------------------------------
__device__ __forceinline__ uint32_t smem_u32(const void* p) {
    uint32_t a;
    asm("{ .reg .u64 t; cvta.to.shared.u64 t, %1; cvt.u32.u64 %0, t; }"
        : "=r"(a) : "l"(p));
    return a;
}
#define CP_ASYNC16(dst, src) \
    asm volatile("cp.async.cg.shared.global [%0], [%1], 16;" \
                 :: "r"(dst), "l"(src) : "memory")
#define CP_COMMIT() asm volatile("cp.async.commit_group;" ::: "memory")
#define CP_WAIT2()  asm volatile("cp.async.wait_group 2;" ::: "memory")
#define CP_WAIT0()  asm volatile("cp.async.wait_group 0;" ::: "memory")

#define LDSM4(r0, r1, r2, r3, addr) \
    asm volatile("ldmatrix.sync.aligned.m8n8.x4.shared.b16 {%0,%1,%2,%3}, [%4];" \
                 : "=r"(r0), "=r"(r1), "=r"(r2), "=r"(r3) : "r"(addr))

#define MMA16816F16(c, a, b) \
    asm volatile("mma.sync.aligned.m16n8k16.row.col.f32.f16.f16.f32 " \
                 "{%0,%1,%2,%3}, {%4,%5,%6,%7}, {%8,%9}, {%0,%1,%2,%3};" \
                 : "+f"((c)[0]), "+f"((c)[1]), "+f"((c)[2]), "+f"((c)[3]) \
                 : "r"((a)[0]), "r"((a)[1]), "r"((a)[2]), "r"((a)[3]), \
                   "r"((b)[0]), "r"((b)[1]))

__device__ __forceinline__ int load_label_dyn(const void* labels, int t) {
    if (g_lab64) return (int)((const long long*)labels)[t];
    return ((const int*)labels)[t];
}

// ---------------------------------------------------------------------------
// Kernel 0 (fused prep): blocks [0,1024) convert A+B -> fp16;
// blocks [1024,2048) transpose+convert W -> fp16; block 2048: label-dtype
// detect (warp-parallel) + zero sort counters (graph replays need the reset).
// ---------------------------------------------------------------------------
__global__ void __launch_bounds__(256)
prep_kernel(const float* __restrict__ A, const float* __restrict__ B,
            const float* __restrict__ W, const void* __restrict__ labels,
            int T) {
    const int b = blockIdx.x;

    if (b < 1024) {
        const int nA4 = E_DIM * D_DIM * R_DIM / 4;   // 128K
        int i = b * 256 + threadIdx.x;
        const float4 v = (i < nA4) ? ((const float4*)A)[i]
                                   : ((const float4*)B)[i - nA4];
        __half2 h01 = __floats2half2_rn(v.x, v.y);
        __half2 h23 = __floats2half2_rn(v.z, v.w);
        uint2 o;
        o.x = *(uint32_t*)&h01;
        o.y = *(uint32_t*)&h23;
        if (i < nA4) ((uint2*)g_a16)[i] = o;
        else         ((uint2*)g_b16)[i - nA4] = o;
        return;
    }
    if (b < 2048) {
        __shared__ float s[32][33];
        const int wid = b - 1024;
        const int k0 = (wid & 31) * 32;
        const int n0 = (wid >> 5) * 32;
        const int tx = threadIdx.x & 31;
        const int ty = threadIdx.x >> 5;
#pragma unroll
        for (int r = 0; r < 4; ++r) {
            int kk = ty + r * 8;
            s[kk][tx] = W[(size_t)(k0 + kk) * D_DIM + n0 + tx];
        }
        __syncthreads();
#pragma unroll
        for (int r = 0; r < 4; ++r) {
            int nn = ty + r * 8;
            __half h = __float2half_rn(s[tx][nn]);
            g_w16[(size_t)(n0 + nn) * D_DIM + k0 + tx] = *(unsigned short*)&h;
        }
        return;
    }
    // ---- block 2048: zero sort counters + label dtype detect ----
    if (threadIdx.x < E_DIM) {
        g_hist[threadIdx.x] = 0;
        g_fill[threadIdx.x] = 0;
    }
    if (threadIdx.x >= 64 && threadIdx.x < 96) {
        const long long* p = (const long long*)labels;
        int n = T < 256 ? T : 256;
        int bad = 0;
        for (int i = threadIdx.x - 64; i < n; i += 32) {
            long long v = p[i];
            if (v < 0 || v >= (1LL << 31)) bad = 1;
        }
        unsigned any_bad = __ballot_sync(0xffffffffu, bad);
        if (threadIdx.x == 64) g_lab64 = (any_bad == 0u) ? 1 : 0;
    }
}

// ---------------------------------------------------------------------------
// Sort kernels: histogram -> exclusive scan -> block-aggregated scatter.
// ---------------------------------------------------------------------------
__global__ void __launch_bounds__(256)
hist_kernel(const void* __restrict__ labels, int T) {
    __shared__ int h[E_DIM];
    if (threadIdx.x < E_DIM) h[threadIdx.x] = 0;
    __syncthreads();
    int t = blockIdx.x * 256 + threadIdx.x;
    if (t < T) atomicAdd(&h[load_label_dyn(labels, t)], 1);
    __syncthreads();
    if (threadIdx.x < E_DIM && h[threadIdx.x] > 0)
        atomicAdd(&g_hist[threadIdx.x], h[threadIdx.x]);
}

__global__ void scan_kernel() {
    if (threadIdx.x != 0 || blockIdx.x != 0) return;
    int run = 0;
    for (int e = 0; e < E_DIM; ++e) { g_off[e] = run; run += g_hist[e]; }
}

__global__ void __launch_bounds__(256)
scatter_kernel(const void* __restrict__ labels, int T) {
    __shared__ int cnt[E_DIM];
    __shared__ int base[E_DIM];
    if (threadIdx.x < E_DIM) cnt[threadIdx.x] = 0;
    __syncthreads();
    int t = blockIdx.x * 256 + threadIdx.x;
    int e = -1, rank = 0;
    if (t < T) {
        e = load_label_dyn(labels, t);
        rank = atomicAdd(&cnt[e], 1);
    }
    __syncthreads();
    if (threadIdx.x < E_DIM && cnt[threadIdx.x] > 0)
        base[threadIdx.x] = g_off[threadIdx.x] +
                            atomicAdd(&g_fill[threadIdx.x], cnt[threadIdx.x]);
    __syncthreads();
    if (t < T) g_sorted[base[e] + rank] = t;
}

// ---------------------------------------------------------------------------
// Kernel 1: fused  x -> fp16  +  xa = x . A16[label], tokens in SORTED order
// (all warps in a block share one expert -> A_e is L1-resident).
// ---------------------------------------------------------------------------
__global__ void __launch_bounds__(256)
convert_x_xa_kernel(const float* __restrict__ x,
                    const void*  __restrict__ labels, int T) {
    int slot = blockIdx.x * 8 + (threadIdx.x >> 5);
    if (slot >= T) return;
    const int t = g_sorted[slot];
    const int lane = threadIdx.x & 31;
    const int e = load_label_dyn(labels, t);
    const float* xrow = x + (size_t)t * D_DIM;
    const unsigned short* Ae = g_a16 + (size_t)e * D_DIM * R_DIM;
    unsigned short* xo = g_x16 + (size_t)t * D_DIM;

    float acc[R_DIM];
#pragma unroll
    for (int r = 0; r < R_DIM; ++r) acc[r] = 0.0f;

#pragma unroll
    for (int i = 0; i < 8; ++i) {
        const int d = i * 128 + lane * 4;
        float4 v = *(const float4*)(xrow + d);
        float vv[4] = {v.x, v.y, v.z, v.w};

        ushort4 h4;
        __half h;
        h = __float2half_rn(vv[0]); h4.x = *(unsigned short*)&h;
        h = __float2half_rn(vv[1]); h4.y = *(unsigned short*)&h;
        h = __float2half_rn(vv[2]); h4.z = *(unsigned short*)&h;
        h = __float2half_rn(vv[3]); h4.w = *(unsigned short*)&h;
        *(ushort4*)(xo + d) = h4;

#pragma unroll
        for (int j = 0; j < 4; ++j) {
            uint4 q = *(const uint4*)(Ae + (size_t)(d + j) * R_DIM);
            float2 f0 = __half22float2(*(__half2*)&q.x);
            float2 f1 = __half22float2(*(__half2*)&q.y);
            float2 f2 = __half22float2(*(__half2*)&q.z);
            float2 f3 = __half22float2(*(__half2*)&q.w);
            float xv = vv[j];
            acc[0] += xv * f0.x;  acc[1] += xv * f0.y;
            acc[2] += xv * f1.x;  acc[3] += xv * f1.y;
            acc[4] += xv * f2.x;  acc[5] += xv * f2.y;
            acc[6] += xv * f3.x;  acc[7] += xv * f3.y;
        }
    }
#pragma unroll
    for (int off = 16; off > 0; off >>= 1)
#pragma unroll
        for (int r = 0; r < R_DIM; ++r)
            acc[r] += __shfl_down_sync(0xffffffffu, acc[r], off);
    if (lane == 0) {
        float4* o = (float4*)(g_xa + (size_t)t * R_DIM);
        o[0] = make_float4(acc[0], acc[1], acc[2], acc[3]);
        o[1] = make_float4(acc[4], acc[5], acc[6], acc[7]);
    }
}

// ---------------------------------------------------------------------------
// Kernel 2: fp16 GEMM + fused LoRA/bias epilogue, rows in SORTED order.
//   512 threads = 16 warps (4M x 4N), warp tile 64x32, BM=256 BN=128.
//   Row gather via s_tok (smem token map); out rows scattered.
// ---------------------------------------------------------------------------
__global__ void __launch_bounds__(512, 1)
gemm_lora_kernel(const void*  __restrict__ labels,
                 const float* __restrict__ bias,
                 float* __restrict__ out) {
    extern __shared__ char smem[];
    const uint32_t sbase = smem_u32(smem);
    int* s_tok = (int*)(smem + TOKMAP_OFF);
    const int tid  = threadIdx.x;
    const int row0 = blockIdx.y * BM;
    const int col0 = blockIdx.x * BN;

    if (tid < 256) s_tok[tid] = g_sorted[row0 + tid];
    __syncthreads();

    const int warp = tid >> 5, lane = tid & 31;
    const int wm = warp >> 2, wn = warp & 3;
    const uint32_t a_lm_base =
        (uint32_t)((wm * 64 + (lane & 15)) * ROWSTRIDE + (lane >> 4) * 8) * 2;
    const uint32_t b_lm_base =
        (uint32_t)((wn * 32 + (lane >> 4) * 8 + (lane & 7)) * ROWSTRIDE +
                   ((lane >> 3) & 1) * 8) * 2;

    float c[4][4][4];                 // 64 accumulators
#pragma unroll
    for (int i = 0; i < 4; ++i)
#pragma unroll
        for (int j = 0; j < 4; ++j)
#pragma unroll
            for (int q = 0; q < 4; ++q) c[i][j][q] = 0.0f;

    auto issue = [&](int cn) {
        const int kk = cn * BKB;
        const uint32_t sa = sbase + (uint32_t)(cn % NSTAGE) * STAGE_BYTES;
#pragma unroll
        for (int i = 0; i < 4; ++i) {
            const int idx = tid + i * 512;
            const int r = idx >> 3, s = idx & 7;
            CP_ASYNC16(sa + OFF_X + (uint32_t)(r * (ROWSTRIDE * 2) + s * 16),
                       g_x16 + (size_t)s_tok[r] * D_DIM + kk + s * 8);
        }
#pragma unroll
        for (int i = 0; i < 2; ++i) {
            const int idx = tid + i * 512;
            const int r = idx >> 3, s = idx & 7;
            CP_ASYNC16(sa + OFF_W + (uint32_t)(r * (ROWSTRIDE * 2) + s * 16),
                       g_w16 + (size_t)(col0 + r) * D_DIM + kk + s * 8);
        }
    };

#pragma unroll
    for (int cn = 0; cn < 3; ++cn) { issue(cn); CP_COMMIT(); }

    for (int ch = 0; ch < NCHUNK; ++ch) {
        CP_WAIT2();
        __syncthreads();

        if (ch + 3 < NCHUNK) { issue(ch + 3); }
        CP_COMMIT();

        const uint32_t sa = sbase + (uint32_t)(ch % NSTAGE) * STAGE_BYTES;

#pragma unroll
        for (int ks = 0; ks < 4; ++ks) {
            uint32_t bfr[4][2];
#pragma unroll
            for (int p = 0; p < 2; ++p) {
                uint32_t bo = b_lm_base + (uint32_t)(p * 16 * ROWSTRIDE + ks * 16) * 2;
                uint32_t r0, r1, r2, r3;
                LDSM4(r0, r1, r2, r3, sa + OFF_W + bo);
                bfr[2 * p][0] = r0;      bfr[2 * p][1] = r1;
                bfr[2 * p + 1][0] = r2;  bfr[2 * p + 1][1] = r3;
            }
            uint32_t afr[4][4];
#pragma unroll
            for (int mf = 0; mf < 4; ++mf) {
                uint32_t ao = a_lm_base + (uint32_t)(mf * 16 * ROWSTRIDE + ks * 16) * 2;
                LDSM4(afr[mf][0], afr[mf][1], afr[mf][2], afr[mf][3], sa + OFF_X + ao);
            }
#pragma unroll
            for (int mf = 0; mf < 4; ++mf)
#pragma unroll
                for (int nf = 0; nf < 4; ++nf)
                    MMA16816F16(c[mf][nf], afr[mf], bfr[nf]);
        }
    }
    CP_WAIT0();
    __syncthreads();

    // ---- stage accumulators to smem (reuse pipeline stage smem) ----
    float* acc_s = (float*)smem;                 // [256][132] = 135 KB
    const int g = lane >> 2, q = lane & 3;
#pragma unroll
    for (int mf = 0; mf < 4; ++mf) {
        const int r1 = wm * 64 + mf * 16 + g;
#pragma unroll
        for (int nf = 0; nf < 4; ++nf) {
            const int cc = wn * 32 + nf * 8 + q * 2;
            *(float2*)&acc_s[r1 * 132 + cc]       = make_float2(c[mf][nf][0], c[mf][nf][1]);
            *(float2*)&acc_s[(r1 + 8) * 132 + cc] = make_float2(c[mf][nf][2], c[mf][nf][3]);
        }
    }
    __syncthreads();

    // ---- epilogue: per-token rank-8 LoRA (fp16 B, L1-hot) + bias ----
    const int lr   = tid >> 1;           // 0..255 (sorted slot within tile)
    const int half = (tid & 1) * 64;     // column half
    const int t    = s_tok[lr];
    const int e    = load_label_dyn(labels, t);

    float xs[R_DIM];
    {
        const float4* p = (const float4*)(g_xa + (size_t)t * R_DIM);
        float4 a0 = p[0], a1 = p[1];
        xs[0] = SCALING * a0.x; xs[1] = SCALING * a0.y;
        xs[2] = SCALING * a0.z; xs[3] = SCALING * a0.w;
        xs[4] = SCALING * a1.x; xs[5] = SCALING * a1.y;
        xs[6] = SCALING * a1.z; xs[7] = SCALING * a1.w;
    }

    const unsigned short* Be = g_b16 + (size_t)e * R_DIM * D_DIM + col0 + half;
    float*       orow = out  + (size_t)t * D_DIM + col0 + half;
    const float* brow = bias + col0 + half;

#pragma unroll
    for (int part = 0; part < 2; ++part) {
        const int pc = part * 32;
        float res[32];
#pragma unroll
        for (int v = 0; v < 8; ++v)
            *(float4*)&res[v * 4] = *(const float4*)&acc_s[lr * 132 + half + pc + v * 4];

#pragma unroll
        for (int r = 0; r < R_DIM; ++r) {
            const uint4* bp = (const uint4*)(Be + (size_t)r * D_DIM + pc);
            const float xr = xs[r];
#pragma unroll
            for (int v = 0; v < 4; ++v) {
                uint4 q4 = bp[v];
                float2 f0 = __half22float2(*(__half2*)&q4.x);
                float2 f1 = __half22float2(*(__half2*)&q4.y);
                float2 f2 = __half22float2(*(__half2*)&q4.z);
                float2 f3 = __half22float2(*(__half2*)&q4.w);
                res[v * 8 + 0] += xr * f0.x;  res[v * 8 + 1] += xr * f0.y;
                res[v * 8 + 2] += xr * f1.x;  res[v * 8 + 3] += xr * f1.y;
                res[v * 8 + 4] += xr * f2.x;  res[v * 8 + 5] += xr * f2.y;
                res[v * 8 + 6] += xr * f3.x;  res[v * 8 + 7] += xr * f3.y;
            }
        }
        const float4* bi = (const float4*)(brow + pc);
#pragma unroll
        for (int v = 0; v < 8; ++v) {
            float4 bv = bi[v];
            float4 o4 = make_float4(res[v * 4 + 0] + bv.x, res[v * 4 + 1] + bv.y,
                                    res[v * 4 + 2] + bv.z, res[v * 4 + 3] + bv.w);
            __stcs((float4*)(orow + pc) + v, o4);   // streaming store
        }
    }
}

// ---------------------------------------------------------------------------
// kernel_launch — graph-capturable, allocation-free.
// Inputs: x, labels, W, A, B, bias
// ---------------------------------------------------------------------------
extern "C" void kernel_launch(void* const* d_in, const int* in_sizes, int n_in,
                              void* d_out, int out_size) {
    const float* x      = (const float*)d_in[0];
    const void*  labels = (const void*) d_in[1];
    const float* W      = (const float*)d_in[2];
    const float* A      = (const float*)d_in[3];
    const float* B      = (const float*)d_in[4];
    const float* bias   = (const float*)d_in[5];
    float* out          = (float*)d_out;

    const int T = in_sizes[0] / D_DIM;
    const int tb = (T + 255) / 256;

    prep_kernel<<<2049, 256>>>(A, B, W, labels, T);
    hist_kernel<<<tb, 256>>>(labels, T);
    scan_kernel<<<1, 32>>>();
    scatter_kernel<<<tb, 256>>>(labels, T);

    convert_x_xa_kernel<<<(T + 7) / 8, 256>>>(x, labels, T);

    static int smem_set = 0;
    if (!smem_set) {
        cudaFuncSetAttribute(gemm_lora_kernel,
                             cudaFuncAttributeMaxDynamicSharedMemorySize, SMEM_BYTES);
        smem_set = 1;
    }
    dim3 grid(D_DIM / BN, T / BM);
    gemm_lora_kernel<<<grid, 512, SMEM_BYTES>>>(labels, bias, out);
}

// round 17
// speedup vs baseline: 2.2561x; 1.0052x over previous
#include <cuda_runtime.h>
#include <cuda_fp16.h>
#include <stdint.h>

// ===========================================================================
// MoE-LoRA fused linear:  y = x @ W + (1/R) * (x @ A[l]) @ B[l] + bias
//   x: [T,D] f32, labels: [T] i32/i64, W: [D,D] f32, A: [E,D,R] f32,
//   B: [E,R,D] f32, bias: [D] f32, out: [T,D] f32.  T=16384 D=1024 R=8 E=64
//
// Round 17 = Round 16 with drain-overlap in the GEMM epilogue (token map,
// label, xa, and bias loads hoisted above the cp.async drain) and minor
// scatter latency trims. Mainloop frozen (legacy-HMMA roofline).
// ===========================================================================

#define D_DIM 1024
#define R_DIM 8
#define SCALING 0.125f
#define MAX_T 16384
#define E_DIM 64

#define BM 256
#define BN 128
#define BKB 64                        // fp16 K per chunk
#define NSTAGE 4
#define NCHUNK 16                     // 1024 / 64
#define ROWSTRIDE 72                  // fp16 per smem row (64 + 8 pad) = 144 B
#define APLANE_BYTES (256 * ROWSTRIDE * 2)    // 36864 (x: 256 rows)
#define BPLANE_BYTES (128 * ROWSTRIDE * 2)    // 18432 (w: 128 rows)
#define OFF_X 0
#define OFF_W (APLANE_BYTES)
#define STAGE_BYTES (APLANE_BYTES + BPLANE_BYTES)   // 55296
#define TOKMAP_OFF (NSTAGE * STAGE_BYTES)           // 221184
#define SMEM_BYTES (TOKMAP_OFF + 256 * 4)           // 222208

// -------------------- device-global scratch (no allocs allowed) ------------
__device__ __align__(256) unsigned short g_x16[MAX_T * D_DIM];   // x fp16
__device__ __align__(256) unsigned short g_w16[D_DIM * D_DIM];   // W^T fp16
__device__ __align__(256) unsigned short g_b16[E_DIM * R_DIM * D_DIM]; // B fp16
__device__ __align__(256) unsigned short g_a16[E_DIM * D_DIM * R_DIM]; // A fp16
__device__ __align__(16)  float          g_xa[MAX_T * R_DIM];
__device__ int g_sorted[MAX_T];
__device__ int g_hist[E_DIM];
__device__ int g_off[E_DIM];
__device__ int g_fill[E_DIM];
__device__ int g_lab64;

// ------------------------------ helpers ------------------------------------
__device__ __forceinline__ uint32_t smem_u32(const void* p) {
    uint32_t a;
    asm("{ .reg .u64 t; cvta.to.shared.u64 t, %1; cvt.u32.u64 %0, t; }"
        : "=r"(a) : "l"(p));
    return a;
}
#define CP_ASYNC16(dst, src) \
    asm volatile("cp.async.cg.shared.global [%0], [%1], 16;" \
                 :: "r"(dst), "l"(src) : "memory")
#define CP_COMMIT() asm volatile("cp.async.commit_group;" ::: "memory")
#define CP_WAIT2()  asm volatile("cp.async.wait_group 2;" ::: "memory")
#define CP_WAIT0()  asm volatile("cp.async.wait_group 0;" ::: "memory")

#define LDSM4(r0, r1, r2, r3, addr) \
    asm volatile("ldmatrix.sync.aligned.m8n8.x4.shared.b16 {%0,%1,%2,%3}, [%4];" \
                 : "=r"(r0), "=r"(r1), "=r"(r2), "=r"(r3) : "r"(addr))

#define MMA16816F16(c, a, b) \
    asm volatile("mma.sync.aligned.m16n8k16.row.col.f32.f16.f16.f32 " \
                 "{%0,%1,%2,%3}, {%4,%5,%6,%7}, {%8,%9}, {%0,%1,%2,%3};" \
                 : "+f"((c)[0]), "+f"((c)[1]), "+f"((c)[2]), "+f"((c)[3]) \
                 : "r"((a)[0]), "r"((a)[1]), "r"((a)[2]), "r"((a)[3]), \
                   "r"((b)[0]), "r"((b)[1]))

__device__ __forceinline__ int load_label_dyn(const void* labels, int t) {
    if (g_lab64) return (int)((const long long*)labels)[t];
    return ((const int*)labels)[t];
}

// ---------------------------------------------------------------------------
// Kernel 0 (fused prep): blocks [0,1024) convert A+B -> fp16;
// blocks [1024,2048) transpose+convert W -> fp16; block 2048: label-dtype
// detect (warp-parallel) + zero sort counters (graph replays need the reset).
// ---------------------------------------------------------------------------
__global__ void __launch_bounds__(256)
prep_kernel(const float* __restrict__ A, const float* __restrict__ B,
            const float* __restrict__ W, const void* __restrict__ labels,
            int T) {
    const int b = blockIdx.x;

    if (b < 1024) {
        const int nA4 = E_DIM * D_DIM * R_DIM / 4;   // 128K
        int i = b * 256 + threadIdx.x;
        const float4 v = (i < nA4) ? ((const float4*)A)[i]
                                   : ((const float4*)B)[i - nA4];
        __half2 h01 = __floats2half2_rn(v.x, v.y);
        __half2 h23 = __floats2half2_rn(v.z, v.w);
        uint2 o;
        o.x = *(uint32_t*)&h01;
        o.y = *(uint32_t*)&h23;
        if (i < nA4) ((uint2*)g_a16)[i] = o;
        else         ((uint2*)g_b16)[i - nA4] = o;
        return;
    }
    if (b < 2048) {
        __shared__ float s[32][33];
        const int wid = b - 1024;
        const int k0 = (wid & 31) * 32;
        const int n0 = (wid >> 5) * 32;
        const int tx = threadIdx.x & 31;
        const int ty = threadIdx.x >> 5;
#pragma unroll
        for (int r = 0; r < 4; ++r) {
            int kk = ty + r * 8;
            s[kk][tx] = W[(size_t)(k0 + kk) * D_DIM + n0 + tx];
        }
        __syncthreads();
#pragma unroll
        for (int r = 0; r < 4; ++r) {
            int nn = ty + r * 8;
            __half h = __float2half_rn(s[tx][nn]);
            g_w16[(size_t)(n0 + nn) * D_DIM + k0 + tx] = *(unsigned short*)&h;
        }
        return;
    }
    // ---- block 2048: zero sort counters + label dtype detect ----
    if (threadIdx.x < E_DIM) {
        g_hist[threadIdx.x] = 0;
        g_fill[threadIdx.x] = 0;
    }
    if (threadIdx.x >= 64 && threadIdx.x < 96) {
        const long long* p = (const long long*)labels;
        int n = T < 256 ? T : 256;
        int bad = 0;
        for (int i = threadIdx.x - 64; i < n; i += 32) {
            long long v = p[i];
            if (v < 0 || v >= (1LL << 31)) bad = 1;
        }
        unsigned any_bad = __ballot_sync(0xffffffffu, bad);
        if (threadIdx.x == 64) g_lab64 = (any_bad == 0u) ? 1 : 0;
    }
}

// ---------------------------------------------------------------------------
// Sort kernels: histogram -> exclusive scan -> block-aggregated scatter.
// ---------------------------------------------------------------------------
__global__ void __launch_bounds__(256)
hist_kernel(const void* __restrict__ labels, int T) {
    __shared__ int h[E_DIM];
    if (threadIdx.x < E_DIM) h[threadIdx.x] = 0;
    __syncthreads();
    int t = blockIdx.x * 256 + threadIdx.x;
    if (t < T) atomicAdd(&h[load_label_dyn(labels, t)], 1);
    __syncthreads();
    if (threadIdx.x < E_DIM && h[threadIdx.x] > 0)
        atomicAdd(&g_hist[threadIdx.x], h[threadIdx.x]);
}

__global__ void scan_kernel() {
    if (threadIdx.x != 0 || blockIdx.x != 0) return;
    int run = 0;
    for (int e = 0; e < E_DIM; ++e) { g_off[e] = run; run += g_hist[e]; }
}

__global__ void __launch_bounds__(256)
scatter_kernel(const void* __restrict__ labels, int T) {
    __shared__ int cnt[E_DIM];
    __shared__ int base[E_DIM];
    if (threadIdx.x < E_DIM) cnt[threadIdx.x] = 0;
    __syncthreads();
    int t = blockIdx.x * 256 + threadIdx.x;
    int e = -1, rank = 0;
    if (t < T) {
        e = load_label_dyn(labels, t);
        rank = atomicAdd(&cnt[e], 1);
    }
    __syncthreads();
    if (threadIdx.x < E_DIM && cnt[threadIdx.x] > 0)
        base[threadIdx.x] = g_off[threadIdx.x] +
                            atomicAdd(&g_fill[threadIdx.x], cnt[threadIdx.x]);
    __syncthreads();
    if (t < T) g_sorted[base[e] + rank] = t;
}

// ---------------------------------------------------------------------------
// Kernel 1: fused  x -> fp16  +  xa = x . A16[label], tokens in SORTED order
// (all warps in a block share one expert -> A_e is L1-resident).
// ---------------------------------------------------------------------------
__global__ void __launch_bounds__(256)
convert_x_xa_kernel(const float* __restrict__ x,
                    const void*  __restrict__ labels, int T) {
    int slot = blockIdx.x * 8 + (threadIdx.x >> 5);
    if (slot >= T) return;
    const int t = g_sorted[slot];
    const int lane = threadIdx.x & 31;
    const int e = load_label_dyn(labels, t);
    const float* xrow = x + (size_t)t * D_DIM;
    const unsigned short* Ae = g_a16 + (size_t)e * D_DIM * R_DIM;
    unsigned short* xo = g_x16 + (size_t)t * D_DIM;

    float acc[R_DIM];
#pragma unroll
    for (int r = 0; r < R_DIM; ++r) acc[r] = 0.0f;

#pragma unroll
    for (int i = 0; i < 8; ++i) {
        const int d = i * 128 + lane * 4;
        float4 v = *(const float4*)(xrow + d);
        float vv[4] = {v.x, v.y, v.z, v.w};

        ushort4 h4;
        __half h;
        h = __float2half_rn(vv[0]); h4.x = *(unsigned short*)&h;
        h = __float2half_rn(vv[1]); h4.y = *(unsigned short*)&h;
        h = __float2half_rn(vv[2]); h4.z = *(unsigned short*)&h;
        h = __float2half_rn(vv[3]); h4.w = *(unsigned short*)&h;
        *(ushort4*)(xo + d) = h4;

#pragma unroll
        for (int j = 0; j < 4; ++j) {
            uint4 q = *(const uint4*)(Ae + (size_t)(d + j) * R_DIM);
            float2 f0 = __half22float2(*(__half2*)&q.x);
            float2 f1 = __half22float2(*(__half2*)&q.y);
            float2 f2 = __half22float2(*(__half2*)&q.z);
            float2 f3 = __half22float2(*(__half2*)&q.w);
            float xv = vv[j];
            acc[0] += xv * f0.x;  acc[1] += xv * f0.y;
            acc[2] += xv * f1.x;  acc[3] += xv * f1.y;
            acc[4] += xv * f2.x;  acc[5] += xv * f2.y;
            acc[6] += xv * f3.x;  acc[7] += xv * f3.y;
        }
    }
#pragma unroll
    for (int off = 16; off > 0; off >>= 1)
#pragma unroll
        for (int r = 0; r < R_DIM; ++r)
            acc[r] += __shfl_down_sync(0xffffffffu, acc[r], off);
    if (lane == 0) {
        float4* o = (float4*)(g_xa + (size_t)t * R_DIM);
        o[0] = make_float4(acc[0], acc[1], acc[2], acc[3]);
        o[1] = make_float4(acc[4], acc[5], acc[6], acc[7]);
    }
}

// ---------------------------------------------------------------------------
// Kernel 2: fp16 GEMM + fused LoRA/bias epilogue, rows in SORTED order.
//   512 threads = 16 warps (4M x 4N), warp tile 64x32, BM=256 BN=128.
//   Epilogue operand loads hoisted above the pipeline drain.
// ---------------------------------------------------------------------------
__global__ void __launch_bounds__(512, 1)
gemm_lora_kernel(const void*  __restrict__ labels,
                 const float* __restrict__ bias,
                 float* __restrict__ out) {
    extern __shared__ char smem[];
    const uint32_t sbase = smem_u32(smem);
    int* s_tok = (int*)(smem + TOKMAP_OFF);
    const int tid  = threadIdx.x;
    const int row0 = blockIdx.y * BM;
    const int col0 = blockIdx.x * BN;

    if (tid < 256) s_tok[tid] = g_sorted[row0 + tid];
    __syncthreads();

    const int warp = tid >> 5, lane = tid & 31;
    const int wm = warp >> 2, wn = warp & 3;
    const uint32_t a_lm_base =
        (uint32_t)((wm * 64 + (lane & 15)) * ROWSTRIDE + (lane >> 4) * 8) * 2;
    const uint32_t b_lm_base =
        (uint32_t)((wn * 32 + (lane >> 4) * 8 + (lane & 7)) * ROWSTRIDE +
                   ((lane >> 3) & 1) * 8) * 2;

    float c[4][4][4];                 // 64 accumulators
#pragma unroll
    for (int i = 0; i < 4; ++i)
#pragma unroll
        for (int j = 0; j < 4; ++j)
#pragma unroll
            for (int q = 0; q < 4; ++q) c[i][j][q] = 0.0f;

    auto issue = [&](int cn) {
        const int kk = cn * BKB;
        const uint32_t sa = sbase + (uint32_t)(cn % NSTAGE) * STAGE_BYTES;
#pragma unroll
        for (int i = 0; i < 4; ++i) {
            const int idx = tid + i * 512;
            const int r = idx >> 3, s = idx & 7;
            CP_ASYNC16(sa + OFF_X + (uint32_t)(r * (ROWSTRIDE * 2) + s * 16),
                       g_x16 + (size_t)s_tok[r] * D_DIM + kk + s * 8);
        }
#pragma unroll
        for (int i = 0; i < 2; ++i) {
            const int idx = tid + i * 512;
            const int r = idx >> 3, s = idx & 7;
            CP_ASYNC16(sa + OFF_W + (uint32_t)(r * (ROWSTRIDE * 2) + s * 16),
                       g_w16 + (size_t)(col0 + r) * D_DIM + kk + s * 8);
        }
    };

#pragma unroll
    for (int cn = 0; cn < 3; ++cn) { issue(cn); CP_COMMIT(); }

    for (int ch = 0; ch < NCHUNK; ++ch) {
        CP_WAIT2();
        __syncthreads();

        if (ch + 3 < NCHUNK) { issue(ch + 3); }
        CP_COMMIT();

        const uint32_t sa = sbase + (uint32_t)(ch % NSTAGE) * STAGE_BYTES;

#pragma unroll
        for (int ks = 0; ks < 4; ++ks) {
            uint32_t bfr[4][2];
#pragma unroll
            for (int p = 0; p < 2; ++p) {
                uint32_t bo = b_lm_base + (uint32_t)(p * 16 * ROWSTRIDE + ks * 16) * 2;
                uint32_t r0, r1, r2, r3;
                LDSM4(r0, r1, r2, r3, sa + OFF_W + bo);
                bfr[2 * p][0] = r0;      bfr[2 * p][1] = r1;
                bfr[2 * p + 1][0] = r2;  bfr[2 * p + 1][1] = r3;
            }
            uint32_t afr[4][4];
#pragma unroll
            for (int mf = 0; mf < 4; ++mf) {
                uint32_t ao = a_lm_base + (uint32_t)(mf * 16 * ROWSTRIDE + ks * 16) * 2;
                LDSM4(afr[mf][0], afr[mf][1], afr[mf][2], afr[mf][3], sa + OFF_X + ao);
            }
#pragma unroll
            for (int mf = 0; mf < 4; ++mf)
#pragma unroll
                for (int nf = 0; nf < 4; ++nf)
                    MMA16816F16(c[mf][nf], afr[mf], bfr[nf]);
        }
    }

    // ---- epilogue operand prefetch BEFORE the drain (overlaps latency) ----
    const int lr   = tid >> 1;           // 0..255 (sorted slot within tile)
    const int half = (tid & 1) * 64;     // column half
    const int t    = s_tok[lr];          // token map region is stable
    const int e    = load_label_dyn(labels, t);

    float xs[R_DIM];
    {
        const float4* p = (const float4*)(g_xa + (size_t)t * R_DIM);
        float4 a0 = p[0], a1 = p[1];
        xs[0] = SCALING * a0.x; xs[1] = SCALING * a0.y;
        xs[2] = SCALING * a0.z; xs[3] = SCALING * a0.w;
        xs[4] = SCALING * a1.x; xs[5] = SCALING * a1.y;
        xs[6] = SCALING * a1.z; xs[7] = SCALING * a1.w;
    }
    float bvals[2][32];
    {
        const float4* bi0 = (const float4*)(bias + col0 + half);
#pragma unroll
        for (int v = 0; v < 8; ++v) *(float4*)&bvals[0][v * 4] = bi0[v];
        const float4* bi1 = (const float4*)(bias + col0 + half + 32);
#pragma unroll
        for (int v = 0; v < 8; ++v) *(float4*)&bvals[1][v * 4] = bi1[v];
    }

    CP_WAIT0();
    __syncthreads();

    // ---- stage accumulators to smem (reuse pipeline stage smem) ----
    float* acc_s = (float*)smem;                 // [256][132] = 135 KB
    const int g = lane >> 2, q = lane & 3;
#pragma unroll
    for (int mf = 0; mf < 4; ++mf) {
        const int r1 = wm * 64 + mf * 16 + g;
#pragma unroll
        for (int nf = 0; nf < 4; ++nf) {
            const int cc = wn * 32 + nf * 8 + q * 2;
            *(float2*)&acc_s[r1 * 132 + cc]       = make_float2(c[mf][nf][0], c[mf][nf][1]);
            *(float2*)&acc_s[(r1 + 8) * 132 + cc] = make_float2(c[mf][nf][2], c[mf][nf][3]);
        }
    }
    __syncthreads();

    // ---- epilogue: per-token rank-8 LoRA (fp16 B, L1-hot) + bias ----
    const unsigned short* Be = g_b16 + (size_t)e * R_DIM * D_DIM + col0 + half;
    float* orow = out + (size_t)t * D_DIM + col0 + half;

#pragma unroll
    for (int part = 0; part < 2; ++part) {
        const int pc = part * 32;
        float res[32];
#pragma unroll
        for (int v = 0; v < 8; ++v)
            *(float4*)&res[v * 4] = *(const float4*)&acc_s[lr * 132 + half + pc + v * 4];

#pragma unroll
        for (int r = 0; r < R_DIM; ++r) {
            const uint4* bp = (const uint4*)(Be + (size_t)r * D_DIM + pc);
            const float xr = xs[r];
#pragma unroll
            for (int v = 0; v < 4; ++v) {
                uint4 q4 = bp[v];
                float2 f0 = __half22float2(*(__half2*)&q4.x);
                float2 f1 = __half22float2(*(__half2*)&q4.y);
                float2 f2 = __half22float2(*(__half2*)&q4.z);
                float2 f3 = __half22float2(*(__half2*)&q4.w);
                res[v * 8 + 0] += xr * f0.x;  res[v * 8 + 1] += xr * f0.y;
                res[v * 8 + 2] += xr * f1.x;  res[v * 8 + 3] += xr * f1.y;
                res[v * 8 + 4] += xr * f2.x;  res[v * 8 + 5] += xr * f2.y;
                res[v * 8 + 6] += xr * f3.x;  res[v * 8 + 7] += xr * f3.y;
            }
        }
#pragma unroll
        for (int v = 0; v < 8; ++v) {
            float4 o4 = make_float4(res[v * 4 + 0] + bvals[part][v * 4 + 0],
                                    res[v * 4 + 1] + bvals[part][v * 4 + 1],
                                    res[v * 4 + 2] + bvals[part][v * 4 + 2],
                                    res[v * 4 + 3] + bvals[part][v * 4 + 3]);
            __stcs((float4*)(orow + pc) + v, o4);   // streaming store
        }
    }
}

// ---------------------------------------------------------------------------
// kernel_launch — graph-capturable, allocation-free.
// Inputs: x, labels, W, A, B, bias
// ---------------------------------------------------------------------------
extern "C" void kernel_launch(void* const* d_in, const int* in_sizes, int n_in,
                              void* d_out, int out_size) {
    const float* x      = (const float*)d_in[0];
    const void*  labels = (const void*) d_in[1];
    const float* W      = (const float*)d_in[2];
    const float* A      = (const float*)d_in[3];
    const float* B      = (const float*)d_in[4];
    const float* bias   = (const float*)d_in[5];
    float* out          = (float*)d_out;

    const int T = in_sizes[0] / D_DIM;
    const int tb = (T + 255) / 256;

    prep_kernel<<<2049, 256>>>(A, B, W, labels, T);
    hist_kernel<<<tb, 256>>>(labels, T);
    scan_kernel<<<1, 32>>>();
    scatter_kernel<<<tb, 256>>>(labels, T);

    convert_x_xa_kernel<<<(T + 7) / 8, 256>>>(x, labels, T);

    static int smem_set = 0;
    if (!smem_set) {
        cudaFuncSetAttribute(gemm_lora_kernel,
                             cudaFuncAttributeMaxDynamicSharedMemorySize, SMEM_BYTES);
        smem_set = 1;
    }
    dim3 grid(D_DIM / BN, T / BM);
    gemm_lora_kernel<<<grid, 512, SMEM_BYTES>>>(labels, bias, out);
}